// round 13
// baseline (speedup 1.0000x reference)
#include <cuda_runtime.h>
#include <cuda_fp16.h>
#include <math.h>

#define D_MODEL 1024
#define N_HEADS 16
#define DH      64
#define BATCH   2
#define SEQ     2048
#define BT      (BATCH * SEQ)      // 4096
#define D3      (3 * D_MODEL)      // 3072

// ---------------- scratch (device globals; no allocation allowed) ----------
__device__ __half g_xh[(size_t)BT * D_MODEL];          // x in fp16
__device__ __half g_winh[(size_t)D3 * D_MODEL];        // W_in fp16
__device__ __half g_wouth[(size_t)D_MODEL * D_MODEL];  // W_out fp16
__device__ __half g_qkvh[(size_t)3 * BT * D_MODEL];    // [3][B*H][T][DH] fp16 (q pre-scaled)
__device__ __half g_attnh[(size_t)BT * D_MODEL];       // [B,T,D] fp16

// ---------------- helpers ----------------------------------------------------
__device__ __forceinline__ unsigned pack_f16x2(float lo, float hi) {
    unsigned r;
    asm("cvt.rn.f16x2.f32 %0, %1, %2;" : "=r"(r) : "f"(hi), "f"(lo));
    return r;
}

__device__ __forceinline__ void mma_f16(
    float& c0, float& c1, float& c2, float& c3,
    unsigned a0, unsigned a1, unsigned a2, unsigned a3,
    unsigned b0, unsigned b1) {
    asm volatile(
        "mma.sync.aligned.m16n8k16.row.col.f32.f16.f16.f32 "
        "{%0,%1,%2,%3}, {%4,%5,%6,%7}, {%8,%9}, {%0,%1,%2,%3};"
        : "+f"(c0), "+f"(c1), "+f"(c2), "+f"(c3)
        : "r"(a0), "r"(a1), "r"(a2), "r"(a3), "r"(b0), "r"(b1));
}

__device__ __forceinline__ void ldsm_x4(
    unsigned& r0, unsigned& r1, unsigned& r2, unsigned& r3, unsigned addr) {
    asm volatile("ldmatrix.sync.aligned.m8n8.x4.shared.b16 {%0,%1,%2,%3}, [%4];"
                 : "=r"(r0), "=r"(r1), "=r"(r2), "=r"(r3) : "r"(addr));
}
__device__ __forceinline__ void ldsm_x4_t(
    unsigned& r0, unsigned& r1, unsigned& r2, unsigned& r3, unsigned addr) {
    asm volatile("ldmatrix.sync.aligned.m8n8.x4.trans.shared.b16 {%0,%1,%2,%3}, [%4];"
                 : "=r"(r0), "=r"(r1), "=r"(r2), "=r"(r3) : "r"(addr));
}

__device__ __forceinline__ unsigned smem_u32_of(const void* p) {
    unsigned r;
    asm("{ .reg .u64 t; cvta.to.shared.u64 t, %1; cvt.u32.u64 %0, t; }"
        : "=r"(r) : "l"(p));
    return r;
}

// ---------------- fp32 -> fp16 prep kernel ------------------------------------
__global__ __launch_bounds__(256) void to_f16_kernel(
    const float* __restrict__ in, __half* __restrict__ out, int n4) {
    int i = blockIdx.x * 256 + threadIdx.x;
    if (i < n4) {
        float4 v = ((const float4*)in)[i];
        uint2 u;
        u.x = pack_f16x2(v.x, v.y);
        u.y = pack_f16x2(v.z, v.w);
        ((uint2*)out)[i] = u;
    }
}

// ---------------- FP16 GEMM: C[M,N] = A[M,K] @ W[N,K]^T ----------------------
// fp16 operands, fp32 accum. Block 128x128, k-step 64, cp.async 3-STAGE
// pipeline (tile i issued at i-2, two k-steps of latency cover), ldmatrix.
#define KSTEP 64
#define HPAD  72
#define OP_BYTES   (128 * HPAD * 2)                    // 18432 per operand
#define STAGE_BYTES (2 * OP_BYTES)                     // 36864
#define GEMM_SMEM_BYTES (3 * STAGE_BYTES)               // 110592

template <int MODE>
__global__ __launch_bounds__(256, 2) void gemm_f16_kernel(
    const __half* __restrict__ A, const __half* __restrict__ W,
    float* __restrict__ C, int M, int N, int K) {
    extern __shared__ char smem[];
    const unsigned smem_u32 = smem_u32_of(smem);

    const int tid  = threadIdx.x;
    const int lane = tid & 31;
    const int wid  = tid >> 5;
    const int warp_m = wid & 3;
    const int warp_n = wid >> 2;
    const int bm = blockIdx.y * 128;
    const int bn = blockIdx.x * 128;
    const int lr = lane >> 2;
    const int lc = lane & 3;

    const int c_row = tid >> 1;            // 0..127
    const int c_ch  = (tid & 1) * 4;       // chunk 0 or 4
    const __half* Abase = A + (size_t)(bm + c_row) * K;
    const __half* Wbase = W + (size_t)(bn + c_row) * K;

    const int a_row = lane & 15;
    const int a_cb  = (lane >> 4) * 16;
    const int b_row = ((lane >> 4) << 3) + (lane & 7);
    const int b_cb  = (lane & 8) ? 16 : 0;

    const unsigned a_base0 = (unsigned)((warp_m * 32 + a_row) * 144 + a_cb);
    const unsigned a_base1 = (unsigned)((warp_m * 32 + 16 + a_row) * 144 + a_cb);
    unsigned b_base[4];
    #pragma unroll
    for (int jn = 0; jn < 4; jn++)
        b_base[jn] = (unsigned)(OP_BYTES + (warp_n * 64 + jn * 16 + b_row) * 144 + b_cb);

#define COPY_TILE(k0, s) {                                                     \
        unsigned base_ = smem_u32 + (unsigned)((s) * STAGE_BYTES);             \
        _Pragma("unroll")                                                      \
        for (int q = 0; q < 4; q++) {                                          \
            int ch_ = c_ch + q;                                                \
            unsigned da_ = base_ + (unsigned)(c_row * 144 + ch_ * 16);         \
            asm volatile("cp.async.cg.shared.global [%0], [%1], 16;"           \
                :: "r"(da_), "l"(Abase + (k0) + ch_ * 8));                     \
            unsigned db_ = base_ + (unsigned)(OP_BYTES + c_row * 144 + ch_ * 16);\
            asm volatile("cp.async.cg.shared.global [%0], [%1], 16;"           \
                :: "r"(db_), "l"(Wbase + (k0) + ch_ * 8));                     \
        }                                                                      \
        asm volatile("cp.async.commit_group;"); }

    float acc[2][8][4];
    #pragma unroll
    for (int i = 0; i < 2; i++)
        #pragma unroll
        for (int j = 0; j < 8; j++)
            #pragma unroll
            for (int c = 0; c < 4; c++) acc[i][j][c] = 0.f;

    const int nk = K / KSTEP;              // 16
    COPY_TILE(0, 0);
    COPY_TILE(KSTEP, 1);

    for (int i = 0; i < nk; i++) {
        if (i + 1 < nk) { asm volatile("cp.async.wait_group 1;"); }
        else            { asm volatile("cp.async.wait_group 0;"); }
        __syncthreads();
        if (i + 2 < nk) {
            const int s2 = (i + 2) % 3;
            COPY_TILE((i + 2) * KSTEP, s2);
        }

        const unsigned sbase = smem_u32 + (unsigned)((i % 3) * STAGE_BYTES);
        #pragma unroll
        for (int kk = 0; kk < 4; kk++) {
            unsigned a[2][4];
            ldsm_x4(a[0][0], a[0][1], a[0][2], a[0][3], sbase + a_base0 + kk * 32);
            ldsm_x4(a[1][0], a[1][1], a[1][2], a[1][3], sbase + a_base1 + kk * 32);
            #pragma unroll
            for (int jn = 0; jn < 4; jn++) {
                unsigned r0, r1, r2, r3;
                ldsm_x4(r0, r1, r2, r3, sbase + b_base[jn] + kk * 32);
                int j0 = 2 * jn, j1 = 2 * jn + 1;
                mma_f16(acc[0][j0][0], acc[0][j0][1], acc[0][j0][2], acc[0][j0][3],
                        a[0][0], a[0][1], a[0][2], a[0][3], r0, r1);
                mma_f16(acc[1][j0][0], acc[1][j0][1], acc[1][j0][2], acc[1][j0][3],
                        a[1][0], a[1][1], a[1][2], a[1][3], r0, r1);
                mma_f16(acc[0][j1][0], acc[0][j1][1], acc[0][j1][2], acc[0][j1][3],
                        a[0][0], a[0][1], a[0][2], a[0][3], r2, r3);
                mma_f16(acc[1][j1][0], acc[1][j1][1], acc[1][j1][2], acc[1][j1][3],
                        a[1][0], a[1][1], a[1][2], a[1][3], r2, r3);
            }
        }
    }
#undef COPY_TILE

    #pragma unroll
    for (int i = 0; i < 2; i++) {
        #pragma unroll
        for (int j = 0; j < 8; j++) {
            #pragma unroll
            for (int half_row = 0; half_row < 2; half_row++) {
                int m = bm + warp_m * 32 + i * 16 + lr + half_row * 8;
                int n = bn + warp_n * 64 + j * 8 + 2 * lc;
                float v0 = acc[i][j][half_row * 2 + 0];
                float v1 = acc[i][j][half_row * 2 + 1];
                if (MODE == 0) {
                    int b = m >> 11;
                    int t = m & (SEQ - 1);
                    int which = n >> 10;
                    int d = n & (D_MODEL - 1);
                    int h = d >> 6;
                    int hd = d & 63;
                    if (which == 0) { v0 *= 0.125f; v1 *= 0.125f; }
                    size_t dst = (size_t)which * ((size_t)BT * D_MODEL) +
                                 (((size_t)(b * N_HEADS + h) * SEQ + t) << 6) + hd;
                    *(unsigned*)((__half*)C + dst) = pack_f16x2(v0, v1);
                } else {
                    C[(size_t)m * N + n]     = v0;
                    C[(size_t)m * N + n + 1] = v1;
                }
            }
        }
    }
}

// ---------------- FP16 tensor-core causal flash attention --------------------
// cp.async 3-STAGE K/V pipeline, ldmatrix everywhere, no P transpose.
#define QT 128
#define KT 64
#define ATT_OP_BYTES   (KT * HPAD * 2)                 // 9216
#define ATT_STAGE_BYTES (2 * ATT_OP_BYTES)             // 18432
#define ATT_SMEM_BYTES  (3 * ATT_STAGE_BYTES)           // 55296

__global__ __launch_bounds__(256) void attn_f16_kernel(
    const __half* __restrict__ qkv, __half* __restrict__ out) {
    extern __shared__ char asmem[];
    const unsigned sm0 = smem_u32_of(asmem);

    const int tid  = threadIdx.x;
    const int lane = tid & 31;
    const int wid  = tid >> 5;
    const int lr = lane >> 2;
    const int lc = lane & 3;

    const int bh = blockIdx.y;
    const int qt = (gridDim.x - 1) - blockIdx.x;   // heavy tiles first
    const int q0 = qt * QT;

    const __half* Qp = qkv + ((size_t)bh * SEQ + q0) * DH;
    const __half* Kp = qkv + (size_t)BT * D_MODEL + (size_t)bh * SEQ * DH;
    const __half* Vp = qkv + (size_t)2 * BT * D_MODEL + (size_t)bh * SEQ * DH;

    const int kb_row = ((lane >> 4) << 3) + (lane & 7);
    const int kb_cb  = (lane & 8) ? 16 : 0;
    const int vb_row = ((lane & 8) ? 8 : 0) + (lane & 7);
    const int vb_cb  = (lane >> 4) * 16;

#define ATT_COPY(k0, s) {                                                      \
        unsigned base_ = sm0 + (unsigned)((s) * ATT_STAGE_BYTES);              \
        _Pragma("unroll")                                                      \
        for (int it = 0; it < 2; it++) {                                       \
            int i_ = tid + 256 * it;                                           \
            int r_ = i_ >> 3;                                                  \
            int ch_ = i_ & 7;                                                  \
            unsigned kd_ = base_ + (unsigned)(r_ * 144 + ch_ * 16);            \
            asm volatile("cp.async.cg.shared.global [%0], [%1], 16;"           \
                :: "r"(kd_), "l"(Kp + (size_t)((k0) + r_) * DH + ch_ * 8));    \
            unsigned vd_ = base_ + (unsigned)(ATT_OP_BYTES + r_ * 144 + ch_ * 16);\
            asm volatile("cp.async.cg.shared.global [%0], [%1], 16;"           \
                :: "r"(vd_), "l"(Vp + (size_t)((k0) + r_) * DH + ch_ * 8));    \
        }                                                                      \
        asm volatile("cp.async.commit_group;"); }

    unsigned qa[4][4];
    {
        const int r0 = wid * 16 + lr;
        #pragma unroll
        for (int kk = 0; kk < 4; kk++) {
            int c = kk * 16 + 2 * lc;
            qa[kk][0] = *(const unsigned*)&Qp[(size_t)r0 * DH + c];
            qa[kk][1] = *(const unsigned*)&Qp[(size_t)(r0 + 8) * DH + c];
            qa[kk][2] = *(const unsigned*)&Qp[(size_t)r0 * DH + c + 8];
            qa[kk][3] = *(const unsigned*)&Qp[(size_t)(r0 + 8) * DH + c + 8];
        }
    }

    float o[8][4];
    #pragma unroll
    for (int n = 0; n < 8; n++)
        #pragma unroll
        for (int c = 0; c < 4; c++) o[n][c] = 0.f;
    float m0 = -1e30f, m1 = -1e30f, l0 = 0.f, l1 = 0.f;

    const int nkt = 2 * qt + 2;
    const int row0 = q0 + wid * 16 + lr;
    const int row1 = row0 + 8;

    ATT_COPY(0, 0);
    if (1 < nkt) ATT_COPY(KT, 1);

    for (int kt = 0; kt < nkt; kt++) {
        const int k0 = kt * KT;
        if (kt + 1 < nkt) { asm volatile("cp.async.wait_group 1;"); }
        else              { asm volatile("cp.async.wait_group 0;"); }
        __syncthreads();
        if (kt + 2 < nkt) {
            const int s2 = (kt + 2) % 3;
            ATT_COPY((kt + 2) * KT, s2);
        }

        const unsigned ksbase = sm0 + (unsigned)((kt % 3) * ATT_STAGE_BYTES);

        // ---- S = (Q/8) @ K^T ----
        float sv[8][4];
        #pragma unroll
        for (int n = 0; n < 8; n++)
            #pragma unroll
            for (int c = 0; c < 4; c++) sv[n][c] = 0.f;

        #pragma unroll
        for (int kk = 0; kk < 4; kk++) {
            #pragma unroll
            for (int jn = 0; jn < 4; jn++) {
                unsigned r0, r1, r2, r3;
                ldsm_x4(r0, r1, r2, r3,
                        ksbase + (unsigned)((jn * 16 + kb_row) * 144 + kk * 32 + kb_cb));
                int n0 = 2 * jn, n1 = 2 * jn + 1;
                mma_f16(sv[n0][0], sv[n0][1], sv[n0][2], sv[n0][3],
                        qa[kk][0], qa[kk][1], qa[kk][2], qa[kk][3], r0, r1);
                mma_f16(sv[n1][0], sv[n1][1], sv[n1][2], sv[n1][3],
                        qa[kk][0], qa[kk][1], qa[kk][2], qa[kk][3], r2, r3);
            }
        }

        if (kt >= 2 * qt) {
            #pragma unroll
            for (int n = 0; n < 8; n++) {
                int col0 = k0 + n * 8 + 2 * lc;
                if (col0 > row0)     sv[n][0] = -1e30f;
                if (col0 + 1 > row0) sv[n][1] = -1e30f;
                if (col0 > row1)     sv[n][2] = -1e30f;
                if (col0 + 1 > row1) sv[n][3] = -1e30f;
            }
        }

        float mx0 = -1e30f, mx1 = -1e30f;
        #pragma unroll
        for (int n = 0; n < 8; n++) {
            mx0 = fmaxf(mx0, fmaxf(sv[n][0], sv[n][1]));
            mx1 = fmaxf(mx1, fmaxf(sv[n][2], sv[n][3]));
        }
        mx0 = fmaxf(mx0, __shfl_xor_sync(0xffffffffu, mx0, 1));
        mx0 = fmaxf(mx0, __shfl_xor_sync(0xffffffffu, mx0, 2));
        mx1 = fmaxf(mx1, __shfl_xor_sync(0xffffffffu, mx1, 1));
        mx1 = fmaxf(mx1, __shfl_xor_sync(0xffffffffu, mx1, 2));

        float mn0 = fmaxf(m0, mx0), mn1 = fmaxf(m1, mx1);
        float alpha0 = __expf(m0 - mn0), alpha1 = __expf(m1 - mn1);
        m0 = mn0; m1 = mn1;

        float sum0 = 0.f, sum1 = 0.f;
        #pragma unroll
        for (int n = 0; n < 8; n++) {
            sv[n][0] = __expf(sv[n][0] - mn0);
            sv[n][1] = __expf(sv[n][1] - mn0);
            sv[n][2] = __expf(sv[n][2] - mn1);
            sv[n][3] = __expf(sv[n][3] - mn1);
            sum0 += sv[n][0] + sv[n][1];
            sum1 += sv[n][2] + sv[n][3];
        }
        sum0 += __shfl_xor_sync(0xffffffffu, sum0, 1);
        sum0 += __shfl_xor_sync(0xffffffffu, sum0, 2);
        sum1 += __shfl_xor_sync(0xffffffffu, sum1, 1);
        sum1 += __shfl_xor_sync(0xffffffffu, sum1, 2);
        l0 = l0 * alpha0 + sum0;
        l1 = l1 * alpha1 + sum1;

        #pragma unroll
        for (int n = 0; n < 8; n++) {
            o[n][0] *= alpha0; o[n][1] *= alpha0;
            o[n][2] *= alpha1; o[n][3] *= alpha1;
        }

        // ---- O += P @ V : P fragments = packed S registers ----
        #pragma unroll
        for (int kk = 0; kk < 4; kk++) {
            unsigned p0 = pack_f16x2(sv[2 * kk][0],     sv[2 * kk][1]);
            unsigned p1 = pack_f16x2(sv[2 * kk][2],     sv[2 * kk][3]);
            unsigned p2 = pack_f16x2(sv[2 * kk + 1][0], sv[2 * kk + 1][1]);
            unsigned p3 = pack_f16x2(sv[2 * kk + 1][2], sv[2 * kk + 1][3]);
            #pragma unroll
            for (int dm = 0; dm < 4; dm++) {
                unsigned r0, r1, r2, r3;
                ldsm_x4_t(r0, r1, r2, r3,
                          ksbase + (unsigned)(ATT_OP_BYTES +
                              (kk * 16 + vb_row) * 144 + dm * 32 + vb_cb));
                int n0 = 2 * dm, n1 = 2 * dm + 1;
                mma_f16(o[n0][0], o[n0][1], o[n0][2], o[n0][3],
                        p0, p1, p2, p3, r0, r1);
                mma_f16(o[n1][0], o[n1][1], o[n1][2], o[n1][3],
                        p0, p1, p2, p3, r2, r3);
            }
        }
    }
#undef ATT_COPY

    const int b = bh >> 4;
    const int h = bh & 15;
    const float inv0 = 1.f / l0;
    const float inv1 = 1.f / l1;
    #pragma unroll
    for (int n = 0; n < 8; n++) {
        int d = h * DH + n * 8 + 2 * lc;
        *(unsigned*)&out[((size_t)(b * SEQ + row0)) * D_MODEL + d] =
            pack_f16x2(o[n][0] * inv0, o[n][1] * inv0);
        *(unsigned*)&out[((size_t)(b * SEQ + row1)) * D_MODEL + d] =
            pack_f16x2(o[n][2] * inv1, o[n][3] * inv1);
    }
}

// ---------------- launch ------------------------------------------------------
extern "C" void kernel_launch(void* const* d_in, const int* in_sizes, int n_in,
                              void* d_out, int out_size) {
    const float* x     = (const float*)d_in[0];
    const float* W_in  = (const float*)d_in[1];
    const float* W_out = (const float*)d_in[2];
    float* out = (float*)d_out;

    __half *xh, *winh, *wouth, *qkvh, *attnh;
    cudaGetSymbolAddress((void**)&xh,    g_xh);
    cudaGetSymbolAddress((void**)&winh,  g_winh);
    cudaGetSymbolAddress((void**)&wouth, g_wouth);
    cudaGetSymbolAddress((void**)&qkvh,  g_qkvh);
    cudaGetSymbolAddress((void**)&attnh, g_attnh);

    cudaFuncSetAttribute(gemm_f16_kernel<0>,
                         cudaFuncAttributeMaxDynamicSharedMemorySize, GEMM_SMEM_BYTES);
    cudaFuncSetAttribute(gemm_f16_kernel<1>,
                         cudaFuncAttributeMaxDynamicSharedMemorySize, GEMM_SMEM_BYTES);
    cudaFuncSetAttribute(attn_f16_kernel,
                         cudaFuncAttributeMaxDynamicSharedMemorySize, ATT_SMEM_BYTES);

    // 0. convert inputs to fp16
    to_f16_kernel<<<(BT * D_MODEL / 4 + 255) / 256, 256>>>(x, xh, BT * D_MODEL / 4);
    to_f16_kernel<<<(D3 * D_MODEL / 4 + 255) / 256, 256>>>(W_in, winh, D3 * D_MODEL / 4);
    to_f16_kernel<<<(D_MODEL * D_MODEL / 4 + 255) / 256, 256>>>(W_out, wouth,
                                                                D_MODEL * D_MODEL / 4);

    // 1. QKV projection (fp16 mma k16, 3-stage cp.async)
    {
        dim3 grid(D3 / 128, BT / 128);        // (24, 32)
        gemm_f16_kernel<0><<<grid, 256, GEMM_SMEM_BYTES>>>(
            xh, winh, (float*)qkvh, BT, D3, D_MODEL);
    }

    // 2. causal flash attention (fp16 mma, 3-stage cp.async)
    {
        dim3 grid(SEQ / QT, BATCH * N_HEADS); // (16, 32)
        attn_f16_kernel<<<grid, 256, ATT_SMEM_BYTES>>>(qkvh, attnh);
    }

    // 3. output projection (fp16 mma, 3-stage) -> fp32 d_out
    {
        dim3 grid(D_MODEL / 128, BT / 128);   // (8, 32)
        gemm_f16_kernel<1><<<grid, 256, GEMM_SMEM_BYTES>>>(
            attnh, wouth, out, BT, D_MODEL, D_MODEL);
    }
}

// round 14
// speedup vs baseline: 1.0615x; 1.0615x over previous
#include <cuda_runtime.h>
#include <cuda_fp16.h>
#include <math.h>

#define D_MODEL 1024
#define N_HEADS 16
#define DH      64
#define BATCH   2
#define SEQ     2048
#define BT      (BATCH * SEQ)      // 4096
#define D3      (3 * D_MODEL)      // 3072

// ---------------- scratch (device globals; no allocation allowed) ----------
__device__ __half g_xh[(size_t)BT * D_MODEL];          // x in fp16
__device__ __half g_winh[(size_t)D3 * D_MODEL];        // W_in fp16
__device__ __half g_wouth[(size_t)D_MODEL * D_MODEL];  // W_out fp16
__device__ __half g_qkvh[(size_t)3 * BT * D_MODEL];    // [3][B*H][T][DH] fp16 (q pre-scaled)
__device__ __half g_attnh[(size_t)BT * D_MODEL];       // [B,T,D] fp16

// ---------------- helpers ----------------------------------------------------
__device__ __forceinline__ unsigned pack_f16x2(float lo, float hi) {
    unsigned r;
    asm("cvt.rn.f16x2.f32 %0, %1, %2;" : "=r"(r) : "f"(hi), "f"(lo));
    return r;
}

__device__ __forceinline__ void mma_f16(
    float& c0, float& c1, float& c2, float& c3,
    unsigned a0, unsigned a1, unsigned a2, unsigned a3,
    unsigned b0, unsigned b1) {
    asm volatile(
        "mma.sync.aligned.m16n8k16.row.col.f32.f16.f16.f32 "
        "{%0,%1,%2,%3}, {%4,%5,%6,%7}, {%8,%9}, {%0,%1,%2,%3};"
        : "+f"(c0), "+f"(c1), "+f"(c2), "+f"(c3)
        : "r"(a0), "r"(a1), "r"(a2), "r"(a3), "r"(b0), "r"(b1));
}

__device__ __forceinline__ void ldsm_x4(
    unsigned& r0, unsigned& r1, unsigned& r2, unsigned& r3, unsigned addr) {
    asm volatile("ldmatrix.sync.aligned.m8n8.x4.shared.b16 {%0,%1,%2,%3}, [%4];"
                 : "=r"(r0), "=r"(r1), "=r"(r2), "=r"(r3) : "r"(addr));
}
__device__ __forceinline__ void ldsm_x4_t(
    unsigned& r0, unsigned& r1, unsigned& r2, unsigned& r3, unsigned addr) {
    asm volatile("ldmatrix.sync.aligned.m8n8.x4.trans.shared.b16 {%0,%1,%2,%3}, [%4];"
                 : "=r"(r0), "=r"(r1), "=r"(r2), "=r"(r3) : "r"(addr));
}

__device__ __forceinline__ unsigned smem_u32_of(const void* p) {
    unsigned r;
    asm("{ .reg .u64 t; cvta.to.shared.u64 t, %1; cvt.u32.u64 %0, t; }"
        : "=r"(r) : "l"(p));
    return r;
}

// ---------------- fused fp32 -> fp16 prep kernel -------------------------------
// Converts x (1M float4), W_in (0.75M float4), W_out (0.25M float4) in ONE grid.
#define X_N4    (BT * D_MODEL / 4)          // 1048576
#define WIN_N4  (D3 * D_MODEL / 4)          // 786432
#define WOUT_N4 (D_MODEL * D_MODEL / 4)     // 262144
#define PREP_N4 (X_N4 + WIN_N4 + WOUT_N4)   // 2097152

__global__ __launch_bounds__(256) void prep_f16_kernel(
    const float* __restrict__ x, const float* __restrict__ w_in,
    const float* __restrict__ w_out,
    __half* __restrict__ xh, __half* __restrict__ winh, __half* __restrict__ wouth) {
    int i = blockIdx.x * 256 + threadIdx.x;
    const float* src;
    __half* dst;
    int off;
    if (i < X_N4)                 { src = x;     dst = xh;    off = i; }
    else if (i < X_N4 + WIN_N4)   { src = w_in;  dst = winh;  off = i - X_N4; }
    else if (i < PREP_N4)         { src = w_out; dst = wouth; off = i - X_N4 - WIN_N4; }
    else return;
    float4 v = ((const float4*)src)[off];
    uint2 u;
    u.x = pack_f16x2(v.x, v.y);
    u.y = pack_f16x2(v.z, v.w);
    ((uint2*)dst)[off] = u;
}

// ---------------- FP16 GEMM (R12 2-stage, measured best) ---------------------
#define KSTEP 64
#define HPAD  72
#define OP_BYTES   (128 * HPAD * 2)                    // 18432 per operand
#define STAGE_BYTES (2 * OP_BYTES)                     // 36864
#define GEMM_SMEM_BYTES (2 * STAGE_BYTES)               // 73728

template <int MODE>
__global__ __launch_bounds__(256, 2) void gemm_f16_kernel(
    const __half* __restrict__ A, const __half* __restrict__ W,
    float* __restrict__ C, int M, int N, int K) {
    extern __shared__ char smem[];
    const unsigned smem_u32 = smem_u32_of(smem);

    const int tid  = threadIdx.x;
    const int lane = tid & 31;
    const int wid  = tid >> 5;
    const int warp_m = wid & 3;
    const int warp_n = wid >> 2;
    const int bm = blockIdx.y * 128;
    const int bn = blockIdx.x * 128;
    const int lr = lane >> 2;
    const int lc = lane & 3;

    const int c_row = tid >> 1;            // 0..127
    const int c_ch  = (tid & 1) * 4;       // chunk 0 or 4
    const __half* Abase = A + (size_t)(bm + c_row) * K;
    const __half* Wbase = W + (size_t)(bn + c_row) * K;

    const int a_row = lane & 15;
    const int a_cb  = (lane >> 4) * 16;
    const int b_row = ((lane >> 4) << 3) + (lane & 7);
    const int b_cb  = (lane & 8) ? 16 : 0;

    const unsigned a_base0 = (unsigned)((warp_m * 32 + a_row) * 144 + a_cb);
    const unsigned a_base1 = (unsigned)((warp_m * 32 + 16 + a_row) * 144 + a_cb);
    unsigned b_base[4];
    #pragma unroll
    for (int jn = 0; jn < 4; jn++)
        b_base[jn] = (unsigned)(OP_BYTES + (warp_n * 64 + jn * 16 + b_row) * 144 + b_cb);

#define COPY_TILE(k0, s) {                                                     \
        unsigned base_ = smem_u32 + (unsigned)((s) * STAGE_BYTES);             \
        _Pragma("unroll")                                                      \
        for (int q = 0; q < 4; q++) {                                          \
            int ch_ = c_ch + q;                                                \
            unsigned da_ = base_ + (unsigned)(c_row * 144 + ch_ * 16);         \
            asm volatile("cp.async.cg.shared.global [%0], [%1], 16;"           \
                :: "r"(da_), "l"(Abase + (k0) + ch_ * 8));                     \
            unsigned db_ = base_ + (unsigned)(OP_BYTES + c_row * 144 + ch_ * 16);\
            asm volatile("cp.async.cg.shared.global [%0], [%1], 16;"           \
                :: "r"(db_), "l"(Wbase + (k0) + ch_ * 8));                     \
        }                                                                      \
        asm volatile("cp.async.commit_group;"); }

    float acc[2][8][4];
    #pragma unroll
    for (int i = 0; i < 2; i++)
        #pragma unroll
        for (int j = 0; j < 8; j++)
            #pragma unroll
            for (int c = 0; c < 4; c++) acc[i][j][c] = 0.f;

    COPY_TILE(0, 0);

    const int nk = K / KSTEP;
    for (int i = 0; i < nk; i++) {
        asm volatile("cp.async.wait_group 0;");
        __syncthreads();
        if (i + 1 < nk) COPY_TILE((i + 1) * KSTEP, (i + 1) & 1);

        const unsigned sbase = smem_u32 + (unsigned)((i & 1) * STAGE_BYTES);
        #pragma unroll
        for (int kk = 0; kk < 4; kk++) {
            unsigned a[2][4];
            ldsm_x4(a[0][0], a[0][1], a[0][2], a[0][3], sbase + a_base0 + kk * 32);
            ldsm_x4(a[1][0], a[1][1], a[1][2], a[1][3], sbase + a_base1 + kk * 32);
            #pragma unroll
            for (int jn = 0; jn < 4; jn++) {
                unsigned r0, r1, r2, r3;
                ldsm_x4(r0, r1, r2, r3, sbase + b_base[jn] + kk * 32);
                int j0 = 2 * jn, j1 = 2 * jn + 1;
                mma_f16(acc[0][j0][0], acc[0][j0][1], acc[0][j0][2], acc[0][j0][3],
                        a[0][0], a[0][1], a[0][2], a[0][3], r0, r1);
                mma_f16(acc[1][j0][0], acc[1][j0][1], acc[1][j0][2], acc[1][j0][3],
                        a[1][0], a[1][1], a[1][2], a[1][3], r0, r1);
                mma_f16(acc[0][j1][0], acc[0][j1][1], acc[0][j1][2], acc[0][j1][3],
                        a[0][0], a[0][1], a[0][2], a[0][3], r2, r3);
                mma_f16(acc[1][j1][0], acc[1][j1][1], acc[1][j1][2], acc[1][j1][3],
                        a[1][0], a[1][1], a[1][2], a[1][3], r2, r3);
            }
        }
    }
#undef COPY_TILE

    #pragma unroll
    for (int i = 0; i < 2; i++) {
        #pragma unroll
        for (int j = 0; j < 8; j++) {
            #pragma unroll
            for (int half_row = 0; half_row < 2; half_row++) {
                int m = bm + warp_m * 32 + i * 16 + lr + half_row * 8;
                int n = bn + warp_n * 64 + j * 8 + 2 * lc;
                float v0 = acc[i][j][half_row * 2 + 0];
                float v1 = acc[i][j][half_row * 2 + 1];
                if (MODE == 0) {
                    int b = m >> 11;
                    int t = m & (SEQ - 1);
                    int which = n >> 10;
                    int d = n & (D_MODEL - 1);
                    int h = d >> 6;
                    int hd = d & 63;
                    if (which == 0) { v0 *= 0.125f; v1 *= 0.125f; }
                    size_t dst = (size_t)which * ((size_t)BT * D_MODEL) +
                                 (((size_t)(b * N_HEADS + h) * SEQ + t) << 6) + hd;
                    *(unsigned*)((__half*)C + dst) = pack_f16x2(v0, v1);
                } else {
                    C[(size_t)m * N + n]     = v0;
                    C[(size_t)m * N + n + 1] = v1;
                }
            }
        }
    }
}

// ---------------- FP16 tensor-core causal flash attention --------------------
// 2-stage cp.async, ldmatrix, no P transpose. Row sums via HMMA with B=ones
// (l computed from quantized fp16 P — consistent with the PV product).
#define QT 128
#define KT 64
#define ATT_OP_BYTES   (KT * HPAD * 2)                 // 9216
#define ATT_STAGE_BYTES (2 * ATT_OP_BYTES)             // 18432
#define ATT_SMEM_BYTES  (2 * ATT_STAGE_BYTES)           // 36864
#define ONES_F16X2 0x3C003C00u

__global__ __launch_bounds__(256) void attn_f16_kernel(
    const __half* __restrict__ qkv, __half* __restrict__ out) {
    extern __shared__ char asmem[];
    const unsigned sm0 = smem_u32_of(asmem);

    const int tid  = threadIdx.x;
    const int lane = tid & 31;
    const int wid  = tid >> 5;
    const int lr = lane >> 2;
    const int lc = lane & 3;

    const int bh = blockIdx.y;
    const int qt = (gridDim.x - 1) - blockIdx.x;   // heavy tiles first
    const int q0 = qt * QT;

    const __half* Qp = qkv + ((size_t)bh * SEQ + q0) * DH;
    const __half* Kp = qkv + (size_t)BT * D_MODEL + (size_t)bh * SEQ * DH;
    const __half* Vp = qkv + (size_t)2 * BT * D_MODEL + (size_t)bh * SEQ * DH;

    const int kb_row = ((lane >> 4) << 3) + (lane & 7);
    const int kb_cb  = (lane & 8) ? 16 : 0;
    const int vb_row = ((lane & 8) ? 8 : 0) + (lane & 7);
    const int vb_cb  = (lane >> 4) * 16;

#define ATT_COPY(k0, s) {                                                      \
        unsigned base_ = sm0 + (unsigned)((s) * ATT_STAGE_BYTES);              \
        _Pragma("unroll")                                                      \
        for (int it = 0; it < 2; it++) {                                       \
            int i_ = tid + 256 * it;                                           \
            int r_ = i_ >> 3;                                                  \
            int ch_ = i_ & 7;                                                  \
            unsigned kd_ = base_ + (unsigned)(r_ * 144 + ch_ * 16);            \
            asm volatile("cp.async.cg.shared.global [%0], [%1], 16;"           \
                :: "r"(kd_), "l"(Kp + (size_t)((k0) + r_) * DH + ch_ * 8));    \
            unsigned vd_ = base_ + (unsigned)(ATT_OP_BYTES + r_ * 144 + ch_ * 16);\
            asm volatile("cp.async.cg.shared.global [%0], [%1], 16;"           \
                :: "r"(vd_), "l"(Vp + (size_t)((k0) + r_) * DH + ch_ * 8));    \
        }                                                                      \
        asm volatile("cp.async.commit_group;"); }

    unsigned qa[4][4];
    {
        const int r0 = wid * 16 + lr;
        #pragma unroll
        for (int kk = 0; kk < 4; kk++) {
            int c = kk * 16 + 2 * lc;
            qa[kk][0] = *(const unsigned*)&Qp[(size_t)r0 * DH + c];
            qa[kk][1] = *(const unsigned*)&Qp[(size_t)(r0 + 8) * DH + c];
            qa[kk][2] = *(const unsigned*)&Qp[(size_t)r0 * DH + c + 8];
            qa[kk][3] = *(const unsigned*)&Qp[(size_t)(r0 + 8) * DH + c + 8];
        }
    }

    float o[8][4];
    #pragma unroll
    for (int n = 0; n < 8; n++)
        #pragma unroll
        for (int c = 0; c < 4; c++) o[n][c] = 0.f;
    float m0 = -1e30f, m1 = -1e30f, l0 = 0.f, l1 = 0.f;

    const int nkt = 2 * qt + 2;
    const int row0 = q0 + wid * 16 + lr;
    const int row1 = row0 + 8;

    ATT_COPY(0, 0);

    for (int kt = 0; kt < nkt; kt++) {
        const int k0 = kt * KT;
        const int s = kt & 1;
        asm volatile("cp.async.wait_group 0;");
        __syncthreads();
        if (kt + 1 < nkt) ATT_COPY((kt + 1) * KT, s ^ 1);

        const unsigned ksbase = sm0 + (unsigned)(s * ATT_STAGE_BYTES);

        // ---- S = (Q/8) @ K^T ----
        float sv[8][4];
        #pragma unroll
        for (int n = 0; n < 8; n++)
            #pragma unroll
            for (int c = 0; c < 4; c++) sv[n][c] = 0.f;

        #pragma unroll
        for (int kk = 0; kk < 4; kk++) {
            #pragma unroll
            for (int jn = 0; jn < 4; jn++) {
                unsigned r0, r1, r2, r3;
                ldsm_x4(r0, r1, r2, r3,
                        ksbase + (unsigned)((jn * 16 + kb_row) * 144 + kk * 32 + kb_cb));
                int n0 = 2 * jn, n1 = 2 * jn + 1;
                mma_f16(sv[n0][0], sv[n0][1], sv[n0][2], sv[n0][3],
                        qa[kk][0], qa[kk][1], qa[kk][2], qa[kk][3], r0, r1);
                mma_f16(sv[n1][0], sv[n1][1], sv[n1][2], sv[n1][3],
                        qa[kk][0], qa[kk][1], qa[kk][2], qa[kk][3], r2, r3);
            }
        }

        if (kt >= 2 * qt) {
            #pragma unroll
            for (int n = 0; n < 8; n++) {
                int col0 = k0 + n * 8 + 2 * lc;
                if (col0 > row0)     sv[n][0] = -1e30f;
                if (col0 + 1 > row0) sv[n][1] = -1e30f;
                if (col0 > row1)     sv[n][2] = -1e30f;
                if (col0 + 1 > row1) sv[n][3] = -1e30f;
            }
        }

        // ---- online softmax: max reduce ----
        float mx0 = -1e30f, mx1 = -1e30f;
        #pragma unroll
        for (int n = 0; n < 8; n++) {
            mx0 = fmaxf(mx0, fmaxf(sv[n][0], sv[n][1]));
            mx1 = fmaxf(mx1, fmaxf(sv[n][2], sv[n][3]));
        }
        mx0 = fmaxf(mx0, __shfl_xor_sync(0xffffffffu, mx0, 1));
        mx0 = fmaxf(mx0, __shfl_xor_sync(0xffffffffu, mx0, 2));
        mx1 = fmaxf(mx1, __shfl_xor_sync(0xffffffffu, mx1, 1));
        mx1 = fmaxf(mx1, __shfl_xor_sync(0xffffffffu, mx1, 2));

        float mn0 = fmaxf(m0, mx0), mn1 = fmaxf(m1, mx1);
        float alpha0 = __expf(m0 - mn0), alpha1 = __expf(m1 - mn1);
        m0 = mn0; m1 = mn1;

        // ---- exp (fp32) then pack to fp16 P fragments ----
        unsigned pfrag[4][4];                 // [kk group][a0..a3]
        #pragma unroll
        for (int n = 0; n < 8; n++) {
            sv[n][0] = __expf(sv[n][0] - mn0);
            sv[n][1] = __expf(sv[n][1] - mn0);
            sv[n][2] = __expf(sv[n][2] - mn1);
            sv[n][3] = __expf(sv[n][3] - mn1);
        }
        #pragma unroll
        for (int kk = 0; kk < 4; kk++) {
            pfrag[kk][0] = pack_f16x2(sv[2 * kk][0],     sv[2 * kk][1]);
            pfrag[kk][1] = pack_f16x2(sv[2 * kk][2],     sv[2 * kk][3]);
            pfrag[kk][2] = pack_f16x2(sv[2 * kk + 1][0], sv[2 * kk + 1][1]);
            pfrag[kk][3] = pack_f16x2(sv[2 * kk + 1][2], sv[2 * kk + 1][3]);
        }

        // ---- row sums via HMMA with B = ones (every lane gets its row sum) --
        float sc0 = 0.f, sc1 = 0.f, sc2 = 0.f, sc3 = 0.f;
        #pragma unroll
        for (int kk = 0; kk < 4; kk++)
            mma_f16(sc0, sc1, sc2, sc3,
                    pfrag[kk][0], pfrag[kk][1], pfrag[kk][2], pfrag[kk][3],
                    ONES_F16X2, ONES_F16X2);
        l0 = l0 * alpha0 + sc0;              // row lr   (all n cols identical)
        l1 = l1 * alpha1 + sc2;              // row lr+8

        #pragma unroll
        for (int n = 0; n < 8; n++) {
            o[n][0] *= alpha0; o[n][1] *= alpha0;
            o[n][2] *= alpha1; o[n][3] *= alpha1;
        }

        // ---- O += P @ V ----
        #pragma unroll
        for (int kk = 0; kk < 4; kk++) {
            #pragma unroll
            for (int dm = 0; dm < 4; dm++) {
                unsigned r0, r1, r2, r3;
                ldsm_x4_t(r0, r1, r2, r3,
                          ksbase + (unsigned)(ATT_OP_BYTES +
                              (kk * 16 + vb_row) * 144 + dm * 32 + vb_cb));
                int n0 = 2 * dm, n1 = 2 * dm + 1;
                mma_f16(o[n0][0], o[n0][1], o[n0][2], o[n0][3],
                        pfrag[kk][0], pfrag[kk][1], pfrag[kk][2], pfrag[kk][3],
                        r0, r1);
                mma_f16(o[n1][0], o[n1][1], o[n1][2], o[n1][3],
                        pfrag[kk][0], pfrag[kk][1], pfrag[kk][2], pfrag[kk][3],
                        r2, r3);
            }
        }
    }
#undef ATT_COPY

    const int b = bh >> 4;
    const int h = bh & 15;
    const float inv0 = 1.f / l0;
    const float inv1 = 1.f / l1;
    #pragma unroll
    for (int n = 0; n < 8; n++) {
        int d = h * DH + n * 8 + 2 * lc;
        *(unsigned*)&out[((size_t)(b * SEQ + row0)) * D_MODEL + d] =
            pack_f16x2(o[n][0] * inv0, o[n][1] * inv0);
        *(unsigned*)&out[((size_t)(b * SEQ + row1)) * D_MODEL + d] =
            pack_f16x2(o[n][2] * inv1, o[n][3] * inv1);
    }
}

// ---------------- launch ------------------------------------------------------
extern "C" void kernel_launch(void* const* d_in, const int* in_sizes, int n_in,
                              void* d_out, int out_size) {
    const float* x     = (const float*)d_in[0];
    const float* W_in  = (const float*)d_in[1];
    const float* W_out = (const float*)d_in[2];
    float* out = (float*)d_out;

    __half *xh, *winh, *wouth, *qkvh, *attnh;
    cudaGetSymbolAddress((void**)&xh,    g_xh);
    cudaGetSymbolAddress((void**)&winh,  g_winh);
    cudaGetSymbolAddress((void**)&wouth, g_wouth);
    cudaGetSymbolAddress((void**)&qkvh,  g_qkvh);
    cudaGetSymbolAddress((void**)&attnh, g_attnh);

    cudaFuncSetAttribute(gemm_f16_kernel<0>,
                         cudaFuncAttributeMaxDynamicSharedMemorySize, GEMM_SMEM_BYTES);
    cudaFuncSetAttribute(gemm_f16_kernel<1>,
                         cudaFuncAttributeMaxDynamicSharedMemorySize, GEMM_SMEM_BYTES);
    cudaFuncSetAttribute(attn_f16_kernel,
                         cudaFuncAttributeMaxDynamicSharedMemorySize, ATT_SMEM_BYTES);

    // 0. fused conversion of all three inputs to fp16
    prep_f16_kernel<<<(PREP_N4 + 255) / 256, 256>>>(x, W_in, W_out, xh, winh, wouth);

    // 1. QKV projection (fp16 mma k16, 2-stage cp.async — measured best)
    {
        dim3 grid(D3 / 128, BT / 128);        // (24, 32)
        gemm_f16_kernel<0><<<grid, 256, GEMM_SMEM_BYTES>>>(
            xh, winh, (float*)qkvh, BT, D3, D_MODEL);
    }

    // 2. causal flash attention (fp16 mma, mma-based row sums)
    {
        dim3 grid(SEQ / QT, BATCH * N_HEADS); // (16, 32)
        attn_f16_kernel<<<grid, 256, ATT_SMEM_BYTES>>>(qkvh, attnh);
    }

    // 3. output projection -> fp32 d_out
    {
        dim3 grid(D_MODEL / 128, BT / 128);   // (8, 32)
        gemm_f16_kernel<1><<<grid, 256, GEMM_SMEM_BYTES>>>(
            attnh, wouth, out, BT, D_MODEL, D_MODEL);
    }
}

// round 15
// speedup vs baseline: 1.1033x; 1.0394x over previous
#include <cuda_runtime.h>
#include <cuda_fp16.h>
#include <math.h>

#define D_MODEL 1024
#define N_HEADS 16
#define DH      64
#define BATCH   2
#define SEQ     2048
#define BT      (BATCH * SEQ)      // 4096
#define D3      (3 * D_MODEL)      // 3072

// ---------------- scratch (device globals; no allocation allowed) ----------
__device__ __half g_xh[(size_t)BT * D_MODEL];          // x in fp16
__device__ __half g_winh[(size_t)D3 * D_MODEL];        // W_in fp16
__device__ __half g_wouth[(size_t)D_MODEL * D_MODEL];  // W_out fp16
__device__ __half g_qkvh[(size_t)3 * BT * D_MODEL];    // [3][B*H][T][DH] fp16 (q pre-scaled)
__device__ __half g_attnh[(size_t)BT * D_MODEL];       // [B,T,D] fp16

// ---------------- helpers ----------------------------------------------------
__device__ __forceinline__ unsigned pack_f16x2(float lo, float hi) {
    unsigned r;
    asm("cvt.rn.f16x2.f32 %0, %1, %2;" : "=r"(r) : "f"(hi), "f"(lo));
    return r;
}

__device__ __forceinline__ void mma_f16(
    float& c0, float& c1, float& c2, float& c3,
    unsigned a0, unsigned a1, unsigned a2, unsigned a3,
    unsigned b0, unsigned b1) {
    asm volatile(
        "mma.sync.aligned.m16n8k16.row.col.f32.f16.f16.f32 "
        "{%0,%1,%2,%3}, {%4,%5,%6,%7}, {%8,%9}, {%0,%1,%2,%3};"
        : "+f"(c0), "+f"(c1), "+f"(c2), "+f"(c3)
        : "r"(a0), "r"(a1), "r"(a2), "r"(a3), "r"(b0), "r"(b1));
}

__device__ __forceinline__ void ldsm_x4(
    unsigned& r0, unsigned& r1, unsigned& r2, unsigned& r3, unsigned addr) {
    asm volatile("ldmatrix.sync.aligned.m8n8.x4.shared.b16 {%0,%1,%2,%3}, [%4];"
                 : "=r"(r0), "=r"(r1), "=r"(r2), "=r"(r3) : "r"(addr));
}
__device__ __forceinline__ void ldsm_x4_t(
    unsigned& r0, unsigned& r1, unsigned& r2, unsigned& r3, unsigned addr) {
    asm volatile("ldmatrix.sync.aligned.m8n8.x4.trans.shared.b16 {%0,%1,%2,%3}, [%4];"
                 : "=r"(r0), "=r"(r1), "=r"(r2), "=r"(r3) : "r"(addr));
}

__device__ __forceinline__ unsigned smem_u32_of(const void* p) {
    unsigned r;
    asm("{ .reg .u64 t; cvta.to.shared.u64 t, %1; cvt.u32.u64 %0, t; }"
        : "=r"(r) : "l"(p));
    return r;
}

// ---------------- fused fp32 -> fp16 prep kernel -------------------------------
#define X_N4    (BT * D_MODEL / 4)          // 1048576
#define WIN_N4  (D3 * D_MODEL / 4)          // 786432
#define WOUT_N4 (D_MODEL * D_MODEL / 4)     // 262144
#define PREP_N4 (X_N4 + WIN_N4 + WOUT_N4)   // 2097152

__global__ __launch_bounds__(256) void prep_f16_kernel(
    const float* __restrict__ x, const float* __restrict__ w_in,
    const float* __restrict__ w_out,
    __half* __restrict__ xh, __half* __restrict__ winh, __half* __restrict__ wouth) {
    int i = blockIdx.x * 256 + threadIdx.x;
    const float* src;
    __half* dst;
    int off;
    if (i < X_N4)                 { src = x;     dst = xh;    off = i; }
    else if (i < X_N4 + WIN_N4)   { src = w_in;  dst = winh;  off = i - X_N4; }
    else if (i < PREP_N4)         { src = w_out; dst = wouth; off = i - X_N4 - WIN_N4; }
    else return;
    float4 v = ((const float4*)src)[off];
    uint2 u;
    u.x = pack_f16x2(v.x, v.y);
    u.y = pack_f16x2(v.z, v.w);
    ((uint2*)dst)[off] = u;
}

// ---------------- FP16 GEMM 128x128 (QKV projection; R12/R14 measured best) --
#define KSTEP 64
#define HPAD  72
#define OP_BYTES   (128 * HPAD * 2)                    // 18432 per operand
#define STAGE_BYTES (2 * OP_BYTES)                     // 36864
#define GEMM_SMEM_BYTES (2 * STAGE_BYTES)               // 73728

__global__ __launch_bounds__(256, 2) void gemm_f16_qkv_kernel(
    const __half* __restrict__ A, const __half* __restrict__ W,
    __half* __restrict__ C, int M, int N, int K) {
    extern __shared__ char smem[];
    const unsigned smem_u32 = smem_u32_of(smem);

    const int tid  = threadIdx.x;
    const int lane = tid & 31;
    const int wid  = tid >> 5;
    const int warp_m = wid & 3;
    const int warp_n = wid >> 2;
    const int bm = blockIdx.y * 128;
    const int bn = blockIdx.x * 128;
    const int lr = lane >> 2;
    const int lc = lane & 3;

    const int c_row = tid >> 1;
    const int c_ch  = (tid & 1) * 4;
    const __half* Abase = A + (size_t)(bm + c_row) * K;
    const __half* Wbase = W + (size_t)(bn + c_row) * K;

    const int a_row = lane & 15;
    const int a_cb  = (lane >> 4) * 16;
    const int b_row = ((lane >> 4) << 3) + (lane & 7);
    const int b_cb  = (lane & 8) ? 16 : 0;

    const unsigned a_base0 = (unsigned)((warp_m * 32 + a_row) * 144 + a_cb);
    const unsigned a_base1 = (unsigned)((warp_m * 32 + 16 + a_row) * 144 + a_cb);
    unsigned b_base[4];
    #pragma unroll
    for (int jn = 0; jn < 4; jn++)
        b_base[jn] = (unsigned)(OP_BYTES + (warp_n * 64 + jn * 16 + b_row) * 144 + b_cb);

#define COPY_TILE(k0, s) {                                                     \
        unsigned base_ = smem_u32 + (unsigned)((s) * STAGE_BYTES);             \
        _Pragma("unroll")                                                      \
        for (int q = 0; q < 4; q++) {                                          \
            int ch_ = c_ch + q;                                                \
            unsigned da_ = base_ + (unsigned)(c_row * 144 + ch_ * 16);         \
            asm volatile("cp.async.cg.shared.global [%0], [%1], 16;"           \
                :: "r"(da_), "l"(Abase + (k0) + ch_ * 8));                     \
            unsigned db_ = base_ + (unsigned)(OP_BYTES + c_row * 144 + ch_ * 16);\
            asm volatile("cp.async.cg.shared.global [%0], [%1], 16;"           \
                :: "r"(db_), "l"(Wbase + (k0) + ch_ * 8));                     \
        }                                                                      \
        asm volatile("cp.async.commit_group;"); }

    float acc[2][8][4];
    #pragma unroll
    for (int i = 0; i < 2; i++)
        #pragma unroll
        for (int j = 0; j < 8; j++)
            #pragma unroll
            for (int c = 0; c < 4; c++) acc[i][j][c] = 0.f;

    COPY_TILE(0, 0);

    const int nk = K / KSTEP;
    for (int i = 0; i < nk; i++) {
        asm volatile("cp.async.wait_group 0;");
        __syncthreads();
        if (i + 1 < nk) COPY_TILE((i + 1) * KSTEP, (i + 1) & 1);

        const unsigned sbase = smem_u32 + (unsigned)((i & 1) * STAGE_BYTES);
        #pragma unroll
        for (int kk = 0; kk < 4; kk++) {
            unsigned a[2][4];
            ldsm_x4(a[0][0], a[0][1], a[0][2], a[0][3], sbase + a_base0 + kk * 32);
            ldsm_x4(a[1][0], a[1][1], a[1][2], a[1][3], sbase + a_base1 + kk * 32);
            #pragma unroll
            for (int jn = 0; jn < 4; jn++) {
                unsigned r0, r1, r2, r3;
                ldsm_x4(r0, r1, r2, r3, sbase + b_base[jn] + kk * 32);
                int j0 = 2 * jn, j1 = 2 * jn + 1;
                mma_f16(acc[0][j0][0], acc[0][j0][1], acc[0][j0][2], acc[0][j0][3],
                        a[0][0], a[0][1], a[0][2], a[0][3], r0, r1);
                mma_f16(acc[1][j0][0], acc[1][j0][1], acc[1][j0][2], acc[1][j0][3],
                        a[1][0], a[1][1], a[1][2], a[1][3], r0, r1);
                mma_f16(acc[0][j1][0], acc[0][j1][1], acc[0][j1][2], acc[0][j1][3],
                        a[0][0], a[0][1], a[0][2], a[0][3], r2, r3);
                mma_f16(acc[1][j1][0], acc[1][j1][1], acc[1][j1][2], acc[1][j1][3],
                        a[1][0], a[1][1], a[1][2], a[1][3], r2, r3);
            }
        }
    }
#undef COPY_TILE

    #pragma unroll
    for (int i = 0; i < 2; i++) {
        #pragma unroll
        for (int j = 0; j < 8; j++) {
            #pragma unroll
            for (int half_row = 0; half_row < 2; half_row++) {
                int m = bm + warp_m * 32 + i * 16 + lr + half_row * 8;
                int n = bn + warp_n * 64 + j * 8 + 2 * lc;
                float v0 = acc[i][j][half_row * 2 + 0];
                float v1 = acc[i][j][half_row * 2 + 1];
                int b = m >> 11;
                int t = m & (SEQ - 1);
                int which = n >> 10;
                int d = n & (D_MODEL - 1);
                int h = d >> 6;
                int hd = d & 63;
                if (which == 0) { v0 *= 0.125f; v1 *= 0.125f; }
                size_t dst = (size_t)which * ((size_t)BT * D_MODEL) +
                             (((size_t)(b * N_HEADS + h) * SEQ + t) << 6) + hd;
                *(unsigned*)&C[dst] = pack_f16x2(v0, v1);
            }
        }
    }
}

// ---------------- FP16 GEMM 64x128 (output projection; small tile, 3 CTA/SM) --
// 8 warps = 2m x 4n, warp tile 32x32, acc 32 regs. Grid (N/128, M/64) = 512 CTAs.
#define SOP_A_BYTES (64 * HPAD * 2)                    // 9216
#define SOP_W_BYTES (128 * HPAD * 2)                   // 18432
#define SSTAGE_BYTES (SOP_A_BYTES + SOP_W_BYTES)       // 27648
#define SGEMM_SMEM_BYTES (2 * SSTAGE_BYTES)             // 55296

__global__ __launch_bounds__(256, 3) void gemm_f16_out_kernel(
    const __half* __restrict__ A, const __half* __restrict__ W,
    float* __restrict__ C, int M, int N, int K) {
    extern __shared__ char smem[];
    const unsigned smem_u32 = smem_u32_of(smem);

    const int tid  = threadIdx.x;
    const int lane = tid & 31;
    const int wid  = tid >> 5;
    const int warp_m = wid & 1;        // 0..1 -> 32-row slice
    const int warp_n = wid >> 1;       // 0..3 -> 32-col slice
    const int bm = blockIdx.y * 64;
    const int bn = blockIdx.x * 128;
    const int lr = lane >> 2;
    const int lc = lane & 3;

    const int a_row = lane & 15;
    const int a_cb  = (lane >> 4) * 16;
    const int b_row = ((lane >> 4) << 3) + (lane & 7);
    const int b_cb  = (lane & 8) ? 16 : 0;

    const unsigned a_base0 = (unsigned)((warp_m * 32 + a_row) * 144 + a_cb);
    const unsigned a_base1 = (unsigned)((warp_m * 32 + 16 + a_row) * 144 + a_cb);
    unsigned b_base[2];
    #pragma unroll
    for (int jn = 0; jn < 2; jn++)
        b_base[jn] = (unsigned)(SOP_A_BYTES + (warp_n * 32 + jn * 16 + b_row) * 144 + b_cb);

    // copy mapping: A 64 rows x 8 chunks = 512 units (2/thread);
    //               W 128 rows x 8 chunks = 1024 units (4/thread)
#define SCOPY_TILE(k0, s) {                                                    \
        unsigned base_ = smem_u32 + (unsigned)((s) * SSTAGE_BYTES);            \
        _Pragma("unroll")                                                      \
        for (int it = 0; it < 2; it++) {                                       \
            int u_ = tid + 256 * it;                                           \
            int r_ = u_ >> 3, ch_ = u_ & 7;                                    \
            unsigned da_ = base_ + (unsigned)(r_ * 144 + ch_ * 16);            \
            asm volatile("cp.async.cg.shared.global [%0], [%1], 16;"           \
                :: "r"(da_), "l"(A + (size_t)(bm + r_) * K + (k0) + ch_ * 8)); \
        }                                                                      \
        _Pragma("unroll")                                                      \
        for (int it = 0; it < 4; it++) {                                       \
            int u_ = tid + 256 * it;                                           \
            int r_ = u_ >> 3, ch_ = u_ & 7;                                    \
            unsigned db_ = base_ + (unsigned)(SOP_A_BYTES + r_ * 144 + ch_ * 16);\
            asm volatile("cp.async.cg.shared.global [%0], [%1], 16;"           \
                :: "r"(db_), "l"(W + (size_t)(bn + r_) * K + (k0) + ch_ * 8)); \
        }                                                                      \
        asm volatile("cp.async.commit_group;"); }

    float acc[2][4][4];
    #pragma unroll
    for (int i = 0; i < 2; i++)
        #pragma unroll
        for (int j = 0; j < 4; j++)
            #pragma unroll
            for (int c = 0; c < 4; c++) acc[i][j][c] = 0.f;

    SCOPY_TILE(0, 0);

    const int nk = K / KSTEP;
    for (int i = 0; i < nk; i++) {
        asm volatile("cp.async.wait_group 0;");
        __syncthreads();
        if (i + 1 < nk) SCOPY_TILE((i + 1) * KSTEP, (i + 1) & 1);

        const unsigned sbase = smem_u32 + (unsigned)((i & 1) * SSTAGE_BYTES);
        #pragma unroll
        for (int kk = 0; kk < 4; kk++) {
            unsigned a[2][4];
            ldsm_x4(a[0][0], a[0][1], a[0][2], a[0][3], sbase + a_base0 + kk * 32);
            ldsm_x4(a[1][0], a[1][1], a[1][2], a[1][3], sbase + a_base1 + kk * 32);
            #pragma unroll
            for (int jn = 0; jn < 2; jn++) {
                unsigned r0, r1, r2, r3;
                ldsm_x4(r0, r1, r2, r3, sbase + b_base[jn] + kk * 32);
                int j0 = 2 * jn, j1 = 2 * jn + 1;
                mma_f16(acc[0][j0][0], acc[0][j0][1], acc[0][j0][2], acc[0][j0][3],
                        a[0][0], a[0][1], a[0][2], a[0][3], r0, r1);
                mma_f16(acc[1][j0][0], acc[1][j0][1], acc[1][j0][2], acc[1][j0][3],
                        a[1][0], a[1][1], a[1][2], a[1][3], r0, r1);
                mma_f16(acc[0][j1][0], acc[0][j1][1], acc[0][j1][2], acc[0][j1][3],
                        a[0][0], a[0][1], a[0][2], a[0][3], r2, r3);
                mma_f16(acc[1][j1][0], acc[1][j1][1], acc[1][j1][2], acc[1][j1][3],
                        a[1][0], a[1][1], a[1][2], a[1][3], r2, r3);
            }
        }
    }
#undef SCOPY_TILE

    #pragma unroll
    for (int i = 0; i < 2; i++) {
        #pragma unroll
        for (int j = 0; j < 4; j++) {
            #pragma unroll
            for (int half_row = 0; half_row < 2; half_row++) {
                int m = bm + warp_m * 32 + i * 16 + lr + half_row * 8;
                int n = bn + warp_n * 32 + j * 8 + 2 * lc;
                C[(size_t)m * N + n]     = acc[i][j][half_row * 2 + 0];
                C[(size_t)m * N + n + 1] = acc[i][j][half_row * 2 + 1];
            }
        }
    }
}

// ---------------- FP16 tensor-core causal flash attention (R14, unchanged) ---
#define QT 128
#define KT 64
#define ATT_OP_BYTES   (KT * HPAD * 2)                 // 9216
#define ATT_STAGE_BYTES (2 * ATT_OP_BYTES)             // 18432
#define ATT_SMEM_BYTES  (2 * ATT_STAGE_BYTES)           // 36864
#define ONES_F16X2 0x3C003C00u

__global__ __launch_bounds__(256) void attn_f16_kernel(
    const __half* __restrict__ qkv, __half* __restrict__ out) {
    extern __shared__ char asmem[];
    const unsigned sm0 = smem_u32_of(asmem);

    const int tid  = threadIdx.x;
    const int lane = tid & 31;
    const int wid  = tid >> 5;
    const int lr = lane >> 2;
    const int lc = lane & 3;

    const int bh = blockIdx.y;
    const int qt = (gridDim.x - 1) - blockIdx.x;   // heavy tiles first
    const int q0 = qt * QT;

    const __half* Qp = qkv + ((size_t)bh * SEQ + q0) * DH;
    const __half* Kp = qkv + (size_t)BT * D_MODEL + (size_t)bh * SEQ * DH;
    const __half* Vp = qkv + (size_t)2 * BT * D_MODEL + (size_t)bh * SEQ * DH;

    const int kb_row = ((lane >> 4) << 3) + (lane & 7);
    const int kb_cb  = (lane & 8) ? 16 : 0;
    const int vb_row = ((lane & 8) ? 8 : 0) + (lane & 7);
    const int vb_cb  = (lane >> 4) * 16;

#define ATT_COPY(k0, s) {                                                      \
        unsigned base_ = sm0 + (unsigned)((s) * ATT_STAGE_BYTES);              \
        _Pragma("unroll")                                                      \
        for (int it = 0; it < 2; it++) {                                       \
            int i_ = tid + 256 * it;                                           \
            int r_ = i_ >> 3;                                                  \
            int ch_ = i_ & 7;                                                  \
            unsigned kd_ = base_ + (unsigned)(r_ * 144 + ch_ * 16);            \
            asm volatile("cp.async.cg.shared.global [%0], [%1], 16;"           \
                :: "r"(kd_), "l"(Kp + (size_t)((k0) + r_) * DH + ch_ * 8));    \
            unsigned vd_ = base_ + (unsigned)(ATT_OP_BYTES + r_ * 144 + ch_ * 16);\
            asm volatile("cp.async.cg.shared.global [%0], [%1], 16;"           \
                :: "r"(vd_), "l"(Vp + (size_t)((k0) + r_) * DH + ch_ * 8));    \
        }                                                                      \
        asm volatile("cp.async.commit_group;"); }

    unsigned qa[4][4];
    {
        const int r0 = wid * 16 + lr;
        #pragma unroll
        for (int kk = 0; kk < 4; kk++) {
            int c = kk * 16 + 2 * lc;
            qa[kk][0] = *(const unsigned*)&Qp[(size_t)r0 * DH + c];
            qa[kk][1] = *(const unsigned*)&Qp[(size_t)(r0 + 8) * DH + c];
            qa[kk][2] = *(const unsigned*)&Qp[(size_t)r0 * DH + c + 8];
            qa[kk][3] = *(const unsigned*)&Qp[(size_t)(r0 + 8) * DH + c + 8];
        }
    }

    float o[8][4];
    #pragma unroll
    for (int n = 0; n < 8; n++)
        #pragma unroll
        for (int c = 0; c < 4; c++) o[n][c] = 0.f;
    float m0 = -1e30f, m1 = -1e30f, l0 = 0.f, l1 = 0.f;

    const int nkt = 2 * qt + 2;
    const int row0 = q0 + wid * 16 + lr;
    const int row1 = row0 + 8;

    ATT_COPY(0, 0);

    for (int kt = 0; kt < nkt; kt++) {
        const int k0 = kt * KT;
        const int s = kt & 1;
        asm volatile("cp.async.wait_group 0;");
        __syncthreads();
        if (kt + 1 < nkt) ATT_COPY((kt + 1) * KT, s ^ 1);

        const unsigned ksbase = sm0 + (unsigned)(s * ATT_STAGE_BYTES);

        float sv[8][4];
        #pragma unroll
        for (int n = 0; n < 8; n++)
            #pragma unroll
            for (int c = 0; c < 4; c++) sv[n][c] = 0.f;

        #pragma unroll
        for (int kk = 0; kk < 4; kk++) {
            #pragma unroll
            for (int jn = 0; jn < 4; jn++) {
                unsigned r0, r1, r2, r3;
                ldsm_x4(r0, r1, r2, r3,
                        ksbase + (unsigned)((jn * 16 + kb_row) * 144 + kk * 32 + kb_cb));
                int n0 = 2 * jn, n1 = 2 * jn + 1;
                mma_f16(sv[n0][0], sv[n0][1], sv[n0][2], sv[n0][3],
                        qa[kk][0], qa[kk][1], qa[kk][2], qa[kk][3], r0, r1);
                mma_f16(sv[n1][0], sv[n1][1], sv[n1][2], sv[n1][3],
                        qa[kk][0], qa[kk][1], qa[kk][2], qa[kk][3], r2, r3);
            }
        }

        if (kt >= 2 * qt) {
            #pragma unroll
            for (int n = 0; n < 8; n++) {
                int col0 = k0 + n * 8 + 2 * lc;
                if (col0 > row0)     sv[n][0] = -1e30f;
                if (col0 + 1 > row0) sv[n][1] = -1e30f;
                if (col0 > row1)     sv[n][2] = -1e30f;
                if (col0 + 1 > row1) sv[n][3] = -1e30f;
            }
        }

        float mx0 = -1e30f, mx1 = -1e30f;
        #pragma unroll
        for (int n = 0; n < 8; n++) {
            mx0 = fmaxf(mx0, fmaxf(sv[n][0], sv[n][1]));
            mx1 = fmaxf(mx1, fmaxf(sv[n][2], sv[n][3]));
        }
        mx0 = fmaxf(mx0, __shfl_xor_sync(0xffffffffu, mx0, 1));
        mx0 = fmaxf(mx0, __shfl_xor_sync(0xffffffffu, mx0, 2));
        mx1 = fmaxf(mx1, __shfl_xor_sync(0xffffffffu, mx1, 1));
        mx1 = fmaxf(mx1, __shfl_xor_sync(0xffffffffu, mx1, 2));

        float mn0 = fmaxf(m0, mx0), mn1 = fmaxf(m1, mx1);
        float alpha0 = __expf(m0 - mn0), alpha1 = __expf(m1 - mn1);
        m0 = mn0; m1 = mn1;

        unsigned pfrag[4][4];
        #pragma unroll
        for (int n = 0; n < 8; n++) {
            sv[n][0] = __expf(sv[n][0] - mn0);
            sv[n][1] = __expf(sv[n][1] - mn0);
            sv[n][2] = __expf(sv[n][2] - mn1);
            sv[n][3] = __expf(sv[n][3] - mn1);
        }
        #pragma unroll
        for (int kk = 0; kk < 4; kk++) {
            pfrag[kk][0] = pack_f16x2(sv[2 * kk][0],     sv[2 * kk][1]);
            pfrag[kk][1] = pack_f16x2(sv[2 * kk][2],     sv[2 * kk][3]);
            pfrag[kk][2] = pack_f16x2(sv[2 * kk + 1][0], sv[2 * kk + 1][1]);
            pfrag[kk][3] = pack_f16x2(sv[2 * kk + 1][2], sv[2 * kk + 1][3]);
        }

        float sc0 = 0.f, sc1 = 0.f, sc2 = 0.f, sc3 = 0.f;
        #pragma unroll
        for (int kk = 0; kk < 4; kk++)
            mma_f16(sc0, sc1, sc2, sc3,
                    pfrag[kk][0], pfrag[kk][1], pfrag[kk][2], pfrag[kk][3],
                    ONES_F16X2, ONES_F16X2);
        l0 = l0 * alpha0 + sc0;
        l1 = l1 * alpha1 + sc2;

        #pragma unroll
        for (int n = 0; n < 8; n++) {
            o[n][0] *= alpha0; o[n][1] *= alpha0;
            o[n][2] *= alpha1; o[n][3] *= alpha1;
        }

        #pragma unroll
        for (int kk = 0; kk < 4; kk++) {
            #pragma unroll
            for (int dm = 0; dm < 4; dm++) {
                unsigned r0, r1, r2, r3;
                ldsm_x4_t(r0, r1, r2, r3,
                          ksbase + (unsigned)(ATT_OP_BYTES +
                              (kk * 16 + vb_row) * 144 + dm * 32 + vb_cb));
                int n0 = 2 * dm, n1 = 2 * dm + 1;
                mma_f16(o[n0][0], o[n0][1], o[n0][2], o[n0][3],
                        pfrag[kk][0], pfrag[kk][1], pfrag[kk][2], pfrag[kk][3],
                        r0, r1);
                mma_f16(o[n1][0], o[n1][1], o[n1][2], o[n1][3],
                        pfrag[kk][0], pfrag[kk][1], pfrag[kk][2], pfrag[kk][3],
                        r2, r3);
            }
        }
    }
#undef ATT_COPY

    const int b = bh >> 4;
    const int h = bh & 15;
    const float inv0 = 1.f / l0;
    const float inv1 = 1.f / l1;
    #pragma unroll
    for (int n = 0; n < 8; n++) {
        int d = h * DH + n * 8 + 2 * lc;
        *(unsigned*)&out[((size_t)(b * SEQ + row0)) * D_MODEL + d] =
            pack_f16x2(o[n][0] * inv0, o[n][1] * inv0);
        *(unsigned*)&out[((size_t)(b * SEQ + row1)) * D_MODEL + d] =
            pack_f16x2(o[n][2] * inv1, o[n][3] * inv1);
    }
}

// ---------------- launch ------------------------------------------------------
extern "C" void kernel_launch(void* const* d_in, const int* in_sizes, int n_in,
                              void* d_out, int out_size) {
    const float* x     = (const float*)d_in[0];
    const float* W_in  = (const float*)d_in[1];
    const float* W_out = (const float*)d_in[2];
    float* out = (float*)d_out;

    __half *xh, *winh, *wouth, *qkvh, *attnh;
    cudaGetSymbolAddress((void**)&xh,    g_xh);
    cudaGetSymbolAddress((void**)&winh,  g_winh);
    cudaGetSymbolAddress((void**)&wouth, g_wouth);
    cudaGetSymbolAddress((void**)&qkvh,  g_qkvh);
    cudaGetSymbolAddress((void**)&attnh, g_attnh);

    cudaFuncSetAttribute(gemm_f16_qkv_kernel,
                         cudaFuncAttributeMaxDynamicSharedMemorySize, GEMM_SMEM_BYTES);
    cudaFuncSetAttribute(gemm_f16_out_kernel,
                         cudaFuncAttributeMaxDynamicSharedMemorySize, SGEMM_SMEM_BYTES);
    cudaFuncSetAttribute(attn_f16_kernel,
                         cudaFuncAttributeMaxDynamicSharedMemorySize, ATT_SMEM_BYTES);

    // 0. fused conversion of all three inputs to fp16
    prep_f16_kernel<<<(PREP_N4 + 255) / 256, 256>>>(x, W_in, W_out, xh, winh, wouth);

    // 1. QKV projection (128x128 tile — measured best for this shape)
    {
        dim3 grid(D3 / 128, BT / 128);        // (24, 32) = 768 CTAs
        gemm_f16_qkv_kernel<<<grid, 256, GEMM_SMEM_BYTES>>>(
            xh, winh, qkvh, BT, D3, D_MODEL);
    }

    // 2. causal flash attention (fp16 mma, mma-based row sums)
    {
        dim3 grid(SEQ / QT, BATCH * N_HEADS); // (16, 32) = 512 CTAs
        attn_f16_kernel<<<grid, 256, ATT_SMEM_BYTES>>>(qkvh, attnh);
    }

    // 3. output projection (64x128 tile, 512 CTAs, 3 CTA/SM) -> fp32 d_out
    {
        dim3 grid(D_MODEL / 128, BT / 64);    // (8, 64) = 512 CTAs
        gemm_f16_out_kernel<<<grid, 256, SGEMM_SMEM_BYTES>>>(
            attnh, wouth, out, BT, D_MODEL, D_MODEL);
    }
}

// round 16
// speedup vs baseline: 1.2598x; 1.1418x over previous
#include <cuda_runtime.h>
#include <cuda_fp16.h>
#include <math.h>

#define D_MODEL 1024
#define N_HEADS 16
#define DH      64
#define BATCH   2
#define SEQ     2048
#define BT      (BATCH * SEQ)      // 4096
#define D3      (3 * D_MODEL)      // 3072

// ---------------- scratch (device globals; no allocation allowed) ----------
__device__ __half g_xh[(size_t)BT * D_MODEL];          // x in fp16
__device__ __half g_winh[(size_t)D3 * D_MODEL];        // W_in fp16
__device__ __half g_wouth[(size_t)D_MODEL * D_MODEL];  // W_out fp16
__device__ __half g_qkvh[(size_t)3 * BT * D_MODEL];    // [3][B*H][T][DH] fp16 (q pre-scaled)
__device__ __half g_attnh[(size_t)BT * D_MODEL];       // [B,T,D] fp16

// ---------------- helpers ----------------------------------------------------
__device__ __forceinline__ unsigned pack_f16x2(float lo, float hi) {
    unsigned r;
    asm("cvt.rn.f16x2.f32 %0, %1, %2;" : "=r"(r) : "f"(hi), "f"(lo));
    return r;
}

__device__ __forceinline__ void mma_f16(
    float& c0, float& c1, float& c2, float& c3,
    unsigned a0, unsigned a1, unsigned a2, unsigned a3,
    unsigned b0, unsigned b1) {
    asm volatile(
        "mma.sync.aligned.m16n8k16.row.col.f32.f16.f16.f32 "
        "{%0,%1,%2,%3}, {%4,%5,%6,%7}, {%8,%9}, {%0,%1,%2,%3};"
        : "+f"(c0), "+f"(c1), "+f"(c2), "+f"(c3)
        : "r"(a0), "r"(a1), "r"(a2), "r"(a3), "r"(b0), "r"(b1));
}

__device__ __forceinline__ void ldsm_x4(
    unsigned& r0, unsigned& r1, unsigned& r2, unsigned& r3, unsigned addr) {
    asm volatile("ldmatrix.sync.aligned.m8n8.x4.shared.b16 {%0,%1,%2,%3}, [%4];"
                 : "=r"(r0), "=r"(r1), "=r"(r2), "=r"(r3) : "r"(addr));
}
__device__ __forceinline__ void ldsm_x4_t(
    unsigned& r0, unsigned& r1, unsigned& r2, unsigned& r3, unsigned addr) {
    asm volatile("ldmatrix.sync.aligned.m8n8.x4.trans.shared.b16 {%0,%1,%2,%3}, [%4];"
                 : "=r"(r0), "=r"(r1), "=r"(r2), "=r"(r3) : "r"(addr));
}

__device__ __forceinline__ unsigned smem_u32_of(const void* p) {
    unsigned r;
    asm("{ .reg .u64 t; cvta.to.shared.u64 t, %1; cvt.u32.u64 %0, t; }"
        : "=r"(r) : "l"(p));
    return r;
}

// ---------------- fused fp32 -> fp16 prep kernel -------------------------------
#define X_N4    (BT * D_MODEL / 4)          // 1048576
#define WIN_N4  (D3 * D_MODEL / 4)          // 786432
#define WOUT_N4 (D_MODEL * D_MODEL / 4)     // 262144
#define PREP_N4 (X_N4 + WIN_N4 + WOUT_N4)   // 2097152

__global__ __launch_bounds__(256) void prep_f16_kernel(
    const float* __restrict__ x, const float* __restrict__ w_in,
    const float* __restrict__ w_out,
    __half* __restrict__ xh, __half* __restrict__ winh, __half* __restrict__ wouth) {
    int i = blockIdx.x * 256 + threadIdx.x;
    const float* src;
    __half* dst;
    int off;
    if (i < X_N4)                 { src = x;     dst = xh;    off = i; }
    else if (i < X_N4 + WIN_N4)   { src = w_in;  dst = winh;  off = i - X_N4; }
    else if (i < PREP_N4)         { src = w_out; dst = wouth; off = i - X_N4 - WIN_N4; }
    else return;
    float4 v = ((const float4*)src)[off];
    uint2 u;
    u.x = pack_f16x2(v.x, v.y);
    u.y = pack_f16x2(v.z, v.w);
    ((uint2*)dst)[off] = u;
}

// ---------------- FP16 GEMM 64x128 tile (both projections) -------------------
// 8 warps = 2m x 4n, warp tile 32x32, acc 32 regs, 3 CTAs/SM, 2-stage cp.async.
// MODE 0: scatter fp16 qkv (q pre-scaled 1/8). MODE 1: fp32 row-major out.
#define KSTEP 64
#define HPAD  72
#define SOP_A_BYTES (64 * HPAD * 2)                    // 9216
#define SOP_W_BYTES (128 * HPAD * 2)                   // 18432
#define SSTAGE_BYTES (SOP_A_BYTES + SOP_W_BYTES)       // 27648
#define SGEMM_SMEM_BYTES (2 * SSTAGE_BYTES)             // 55296

template <int MODE>
__global__ __launch_bounds__(256, 3) void gemm_f16_kernel(
    const __half* __restrict__ A, const __half* __restrict__ W,
    float* __restrict__ C, int M, int N, int K) {
    extern __shared__ char smem[];
    const unsigned smem_u32 = smem_u32_of(smem);

    const int tid  = threadIdx.x;
    const int lane = tid & 31;
    const int wid  = tid >> 5;
    const int warp_m = wid & 1;        // 0..1 -> 32-row slice
    const int warp_n = wid >> 1;       // 0..3 -> 32-col slice
    const int bm = blockIdx.y * 64;
    const int bn = blockIdx.x * 128;
    const int lr = lane >> 2;
    const int lc = lane & 3;

    const int a_row = lane & 15;
    const int a_cb  = (lane >> 4) * 16;
    const int b_row = ((lane >> 4) << 3) + (lane & 7);
    const int b_cb  = (lane & 8) ? 16 : 0;

    const unsigned a_base0 = (unsigned)((warp_m * 32 + a_row) * 144 + a_cb);
    const unsigned a_base1 = (unsigned)((warp_m * 32 + 16 + a_row) * 144 + a_cb);
    unsigned b_base[2];
    #pragma unroll
    for (int jn = 0; jn < 2; jn++)
        b_base[jn] = (unsigned)(SOP_A_BYTES + (warp_n * 32 + jn * 16 + b_row) * 144 + b_cb);

#define SCOPY_TILE(k0, s) {                                                    \
        unsigned base_ = smem_u32 + (unsigned)((s) * SSTAGE_BYTES);            \
        _Pragma("unroll")                                                      \
        for (int it = 0; it < 2; it++) {                                       \
            int u_ = tid + 256 * it;                                           \
            int r_ = u_ >> 3, ch_ = u_ & 7;                                    \
            unsigned da_ = base_ + (unsigned)(r_ * 144 + ch_ * 16);            \
            asm volatile("cp.async.cg.shared.global [%0], [%1], 16;"           \
                :: "r"(da_), "l"(A + (size_t)(bm + r_) * K + (k0) + ch_ * 8)); \
        }                                                                      \
        _Pragma("unroll")                                                      \
        for (int it = 0; it < 4; it++) {                                       \
            int u_ = tid + 256 * it;                                           \
            int r_ = u_ >> 3, ch_ = u_ & 7;                                    \
            unsigned db_ = base_ + (unsigned)(SOP_A_BYTES + r_ * 144 + ch_ * 16);\
            asm volatile("cp.async.cg.shared.global [%0], [%1], 16;"           \
                :: "r"(db_), "l"(W + (size_t)(bn + r_) * K + (k0) + ch_ * 8)); \
        }                                                                      \
        asm volatile("cp.async.commit_group;"); }

    float acc[2][4][4];
    #pragma unroll
    for (int i = 0; i < 2; i++)
        #pragma unroll
        for (int j = 0; j < 4; j++)
            #pragma unroll
            for (int c = 0; c < 4; c++) acc[i][j][c] = 0.f;

    SCOPY_TILE(0, 0);

    const int nk = K / KSTEP;
    for (int i = 0; i < nk; i++) {
        asm volatile("cp.async.wait_group 0;");
        __syncthreads();
        if (i + 1 < nk) SCOPY_TILE((i + 1) * KSTEP, (i + 1) & 1);

        const unsigned sbase = smem_u32 + (unsigned)((i & 1) * SSTAGE_BYTES);
        #pragma unroll
        for (int kk = 0; kk < 4; kk++) {
            unsigned a[2][4];
            ldsm_x4(a[0][0], a[0][1], a[0][2], a[0][3], sbase + a_base0 + kk * 32);
            ldsm_x4(a[1][0], a[1][1], a[1][2], a[1][3], sbase + a_base1 + kk * 32);
            #pragma unroll
            for (int jn = 0; jn < 2; jn++) {
                unsigned r0, r1, r2, r3;
                ldsm_x4(r0, r1, r2, r3, sbase + b_base[jn] + kk * 32);
                int j0 = 2 * jn, j1 = 2 * jn + 1;
                mma_f16(acc[0][j0][0], acc[0][j0][1], acc[0][j0][2], acc[0][j0][3],
                        a[0][0], a[0][1], a[0][2], a[0][3], r0, r1);
                mma_f16(acc[1][j0][0], acc[1][j0][1], acc[1][j0][2], acc[1][j0][3],
                        a[1][0], a[1][1], a[1][2], a[1][3], r0, r1);
                mma_f16(acc[0][j1][0], acc[0][j1][1], acc[0][j1][2], acc[0][j1][3],
                        a[0][0], a[0][1], a[0][2], a[0][3], r2, r3);
                mma_f16(acc[1][j1][0], acc[1][j1][1], acc[1][j1][2], acc[1][j1][3],
                        a[1][0], a[1][1], a[1][2], a[1][3], r2, r3);
            }
        }
    }
#undef SCOPY_TILE

    #pragma unroll
    for (int i = 0; i < 2; i++) {
        #pragma unroll
        for (int j = 0; j < 4; j++) {
            #pragma unroll
            for (int half_row = 0; half_row < 2; half_row++) {
                int m = bm + warp_m * 32 + i * 16 + lr + half_row * 8;
                int n = bn + warp_n * 32 + j * 8 + 2 * lc;
                float v0 = acc[i][j][half_row * 2 + 0];
                float v1 = acc[i][j][half_row * 2 + 1];
                if (MODE == 0) {
                    int b = m >> 11;
                    int t = m & (SEQ - 1);
                    int which = n >> 10;
                    int d = n & (D_MODEL - 1);
                    int h = d >> 6;
                    int hd = d & 63;
                    if (which == 0) { v0 *= 0.125f; v1 *= 0.125f; }
                    size_t dst = (size_t)which * ((size_t)BT * D_MODEL) +
                                 (((size_t)(b * N_HEADS + h) * SEQ + t) << 6) + hd;
                    *(unsigned*)((__half*)C + dst) = pack_f16x2(v0, v1);
                } else {
                    C[(size_t)m * N + n]     = v0;
                    C[(size_t)m * N + n + 1] = v1;
                }
            }
        }
    }
}

// ---------------- FP16 tensor-core causal flash attention (R14, unchanged) ---
#define QT 128
#define KT 64
#define ATT_OP_BYTES   (KT * HPAD * 2)                 // 9216
#define ATT_STAGE_BYTES (2 * ATT_OP_BYTES)             // 18432
#define ATT_SMEM_BYTES  (2 * ATT_STAGE_BYTES)           // 36864
#define ONES_F16X2 0x3C003C00u

__global__ __launch_bounds__(256) void attn_f16_kernel(
    const __half* __restrict__ qkv, __half* __restrict__ out) {
    extern __shared__ char asmem[];
    const unsigned sm0 = smem_u32_of(asmem);

    const int tid  = threadIdx.x;
    const int lane = tid & 31;
    const int wid  = tid >> 5;
    const int lr = lane >> 2;
    const int lc = lane & 3;

    const int bh = blockIdx.y;
    const int qt = (gridDim.x - 1) - blockIdx.x;   // heavy tiles first
    const int q0 = qt * QT;

    const __half* Qp = qkv + ((size_t)bh * SEQ + q0) * DH;
    const __half* Kp = qkv + (size_t)BT * D_MODEL + (size_t)bh * SEQ * DH;
    const __half* Vp = qkv + (size_t)2 * BT * D_MODEL + (size_t)bh * SEQ * DH;

    const int kb_row = ((lane >> 4) << 3) + (lane & 7);
    const int kb_cb  = (lane & 8) ? 16 : 0;
    const int vb_row = ((lane & 8) ? 8 : 0) + (lane & 7);
    const int vb_cb  = (lane >> 4) * 16;

#define ATT_COPY(k0, s) {                                                      \
        unsigned base_ = sm0 + (unsigned)((s) * ATT_STAGE_BYTES);              \
        _Pragma("unroll")                                                      \
        for (int it = 0; it < 2; it++) {                                       \
            int i_ = tid + 256 * it;                                           \
            int r_ = i_ >> 3;                                                  \
            int ch_ = i_ & 7;                                                  \
            unsigned kd_ = base_ + (unsigned)(r_ * 144 + ch_ * 16);            \
            asm volatile("cp.async.cg.shared.global [%0], [%1], 16;"           \
                :: "r"(kd_), "l"(Kp + (size_t)((k0) + r_) * DH + ch_ * 8));    \
            unsigned vd_ = base_ + (unsigned)(ATT_OP_BYTES + r_ * 144 + ch_ * 16);\
            asm volatile("cp.async.cg.shared.global [%0], [%1], 16;"           \
                :: "r"(vd_), "l"(Vp + (size_t)((k0) + r_) * DH + ch_ * 8));    \
        }                                                                      \
        asm volatile("cp.async.commit_group;"); }

    unsigned qa[4][4];
    {
        const int r0 = wid * 16 + lr;
        #pragma unroll
        for (int kk = 0; kk < 4; kk++) {
            int c = kk * 16 + 2 * lc;
            qa[kk][0] = *(const unsigned*)&Qp[(size_t)r0 * DH + c];
            qa[kk][1] = *(const unsigned*)&Qp[(size_t)(r0 + 8) * DH + c];
            qa[kk][2] = *(const unsigned*)&Qp[(size_t)r0 * DH + c + 8];
            qa[kk][3] = *(const unsigned*)&Qp[(size_t)(r0 + 8) * DH + c + 8];
        }
    }

    float o[8][4];
    #pragma unroll
    for (int n = 0; n < 8; n++)
        #pragma unroll
        for (int c = 0; c < 4; c++) o[n][c] = 0.f;
    float m0 = -1e30f, m1 = -1e30f, l0 = 0.f, l1 = 0.f;

    const int nkt = 2 * qt + 2;
    const int row0 = q0 + wid * 16 + lr;
    const int row1 = row0 + 8;

    ATT_COPY(0, 0);

    for (int kt = 0; kt < nkt; kt++) {
        const int k0 = kt * KT;
        const int s = kt & 1;
        asm volatile("cp.async.wait_group 0;");
        __syncthreads();
        if (kt + 1 < nkt) ATT_COPY((kt + 1) * KT, s ^ 1);

        const unsigned ksbase = sm0 + (unsigned)(s * ATT_STAGE_BYTES);

        float sv[8][4];
        #pragma unroll
        for (int n = 0; n < 8; n++)
            #pragma unroll
            for (int c = 0; c < 4; c++) sv[n][c] = 0.f;

        #pragma unroll
        for (int kk = 0; kk < 4; kk++) {
            #pragma unroll
            for (int jn = 0; jn < 4; jn++) {
                unsigned r0, r1, r2, r3;
                ldsm_x4(r0, r1, r2, r3,
                        ksbase + (unsigned)((jn * 16 + kb_row) * 144 + kk * 32 + kb_cb));
                int n0 = 2 * jn, n1 = 2 * jn + 1;
                mma_f16(sv[n0][0], sv[n0][1], sv[n0][2], sv[n0][3],
                        qa[kk][0], qa[kk][1], qa[kk][2], qa[kk][3], r0, r1);
                mma_f16(sv[n1][0], sv[n1][1], sv[n1][2], sv[n1][3],
                        qa[kk][0], qa[kk][1], qa[kk][2], qa[kk][3], r2, r3);
            }
        }

        if (kt >= 2 * qt) {
            #pragma unroll
            for (int n = 0; n < 8; n++) {
                int col0 = k0 + n * 8 + 2 * lc;
                if (col0 > row0)     sv[n][0] = -1e30f;
                if (col0 + 1 > row0) sv[n][1] = -1e30f;
                if (col0 > row1)     sv[n][2] = -1e30f;
                if (col0 + 1 > row1) sv[n][3] = -1e30f;
            }
        }

        float mx0 = -1e30f, mx1 = -1e30f;
        #pragma unroll
        for (int n = 0; n < 8; n++) {
            mx0 = fmaxf(mx0, fmaxf(sv[n][0], sv[n][1]));
            mx1 = fmaxf(mx1, fmaxf(sv[n][2], sv[n][3]));
        }
        mx0 = fmaxf(mx0, __shfl_xor_sync(0xffffffffu, mx0, 1));
        mx0 = fmaxf(mx0, __shfl_xor_sync(0xffffffffu, mx0, 2));
        mx1 = fmaxf(mx1, __shfl_xor_sync(0xffffffffu, mx1, 1));
        mx1 = fmaxf(mx1, __shfl_xor_sync(0xffffffffu, mx1, 2));

        float mn0 = fmaxf(m0, mx0), mn1 = fmaxf(m1, mx1);
        float alpha0 = __expf(m0 - mn0), alpha1 = __expf(m1 - mn1);
        m0 = mn0; m1 = mn1;

        unsigned pfrag[4][4];
        #pragma unroll
        for (int n = 0; n < 8; n++) {
            sv[n][0] = __expf(sv[n][0] - mn0);
            sv[n][1] = __expf(sv[n][1] - mn0);
            sv[n][2] = __expf(sv[n][2] - mn1);
            sv[n][3] = __expf(sv[n][3] - mn1);
        }
        #pragma unroll
        for (int kk = 0; kk < 4; kk++) {
            pfrag[kk][0] = pack_f16x2(sv[2 * kk][0],     sv[2 * kk][1]);
            pfrag[kk][1] = pack_f16x2(sv[2 * kk][2],     sv[2 * kk][3]);
            pfrag[kk][2] = pack_f16x2(sv[2 * kk + 1][0], sv[2 * kk + 1][1]);
            pfrag[kk][3] = pack_f16x2(sv[2 * kk + 1][2], sv[2 * kk + 1][3]);
        }

        float sc0 = 0.f, sc1 = 0.f, sc2 = 0.f, sc3 = 0.f;
        #pragma unroll
        for (int kk = 0; kk < 4; kk++)
            mma_f16(sc0, sc1, sc2, sc3,
                    pfrag[kk][0], pfrag[kk][1], pfrag[kk][2], pfrag[kk][3],
                    ONES_F16X2, ONES_F16X2);
        l0 = l0 * alpha0 + sc0;
        l1 = l1 * alpha1 + sc2;

        #pragma unroll
        for (int n = 0; n < 8; n++) {
            o[n][0] *= alpha0; o[n][1] *= alpha0;
            o[n][2] *= alpha1; o[n][3] *= alpha1;
        }

        #pragma unroll
        for (int kk = 0; kk < 4; kk++) {
            #pragma unroll
            for (int dm = 0; dm < 4; dm++) {
                unsigned r0, r1, r2, r3;
                ldsm_x4_t(r0, r1, r2, r3,
                          ksbase + (unsigned)(ATT_OP_BYTES +
                              (kk * 16 + vb_row) * 144 + dm * 32 + vb_cb));
                int n0 = 2 * dm, n1 = 2 * dm + 1;
                mma_f16(o[n0][0], o[n0][1], o[n0][2], o[n0][3],
                        pfrag[kk][0], pfrag[kk][1], pfrag[kk][2], pfrag[kk][3],
                        r0, r1);
                mma_f16(o[n1][0], o[n1][1], o[n1][2], o[n1][3],
                        pfrag[kk][0], pfrag[kk][1], pfrag[kk][2], pfrag[kk][3],
                        r2, r3);
            }
        }
    }
#undef ATT_COPY

    const int b = bh >> 4;
    const int h = bh & 15;
    const float inv0 = 1.f / l0;
    const float inv1 = 1.f / l1;
    #pragma unroll
    for (int n = 0; n < 8; n++) {
        int d = h * DH + n * 8 + 2 * lc;
        *(unsigned*)&out[((size_t)(b * SEQ + row0)) * D_MODEL + d] =
            pack_f16x2(o[n][0] * inv0, o[n][1] * inv0);
        *(unsigned*)&out[((size_t)(b * SEQ + row1)) * D_MODEL + d] =
            pack_f16x2(o[n][2] * inv1, o[n][3] * inv1);
    }
}

// ---------------- launch ------------------------------------------------------
extern "C" void kernel_launch(void* const* d_in, const int* in_sizes, int n_in,
                              void* d_out, int out_size) {
    const float* x     = (const float*)d_in[0];
    const float* W_in  = (const float*)d_in[1];
    const float* W_out = (const float*)d_in[2];
    float* out = (float*)d_out;

    __half *xh, *winh, *wouth, *qkvh, *attnh;
    cudaGetSymbolAddress((void**)&xh,    g_xh);
    cudaGetSymbolAddress((void**)&winh,  g_winh);
    cudaGetSymbolAddress((void**)&wouth, g_wouth);
    cudaGetSymbolAddress((void**)&qkvh,  g_qkvh);
    cudaGetSymbolAddress((void**)&attnh, g_attnh);

    cudaFuncSetAttribute(gemm_f16_kernel<0>,
                         cudaFuncAttributeMaxDynamicSharedMemorySize, SGEMM_SMEM_BYTES);
    cudaFuncSetAttribute(gemm_f16_kernel<1>,
                         cudaFuncAttributeMaxDynamicSharedMemorySize, SGEMM_SMEM_BYTES);
    cudaFuncSetAttribute(attn_f16_kernel,
                         cudaFuncAttributeMaxDynamicSharedMemorySize, ATT_SMEM_BYTES);

    // 0. fused conversion of all three inputs to fp16
    prep_f16_kernel<<<(PREP_N4 + 255) / 256, 256>>>(x, W_in, W_out, xh, winh, wouth);

    // 1. QKV projection (64x128 tile, 3 CTA/SM — the measured-faster shape)
    {
        dim3 grid(D3 / 128, BT / 64);         // (24, 64) = 1536 CTAs
        gemm_f16_kernel<0><<<grid, 256, SGEMM_SMEM_BYTES>>>(
            xh, winh, (float*)qkvh, BT, D3, D_MODEL);
    }

    // 2. causal flash attention (fp16 mma, mma-based row sums)
    {
        dim3 grid(SEQ / QT, BATCH * N_HEADS); // (16, 32) = 512 CTAs
        attn_f16_kernel<<<grid, 256, ATT_SMEM_BYTES>>>(qkvh, attnh);
    }

    // 3. output projection (64x128 tile) -> fp32 d_out
    {
        dim3 grid(D_MODEL / 128, BT / 64);    // (8, 64) = 512 CTAs
        gemm_f16_kernel<1><<<grid, 256, SGEMM_SMEM_BYTES>>>(
            attnh, wouth, out, BT, D_MODEL, D_MODEL);
    }
}

// round 17
// speedup vs baseline: 1.2846x; 1.0197x over previous
#include <cuda_runtime.h>
#include <cuda_fp16.h>
#include <math.h>

#define D_MODEL 1024
#define N_HEADS 16
#define DH      64
#define BATCH   2
#define SEQ     2048
#define BT      (BATCH * SEQ)      // 4096
#define D3      (3 * D_MODEL)      // 3072

// ---------------- scratch (device globals; no allocation allowed) ----------
__device__ __half g_xh[(size_t)BT * D_MODEL];          // x in fp16
__device__ __half g_winh[(size_t)D3 * D_MODEL];        // W_in fp16
__device__ __half g_wouth[(size_t)D_MODEL * D_MODEL];  // W_out fp16
__device__ __half g_qkvh[(size_t)3 * BT * D_MODEL];    // [3][B*H][T][DH] fp16 (q pre-scaled)
__device__ __half g_attnh[(size_t)BT * D_MODEL];       // [B,T,D] fp16

// ---------------- helpers ----------------------------------------------------
__device__ __forceinline__ unsigned pack_f16x2(float lo, float hi) {
    unsigned r;
    asm("cvt.rn.f16x2.f32 %0, %1, %2;" : "=r"(r) : "f"(hi), "f"(lo));
    return r;
}

__device__ __forceinline__ unsigned ex2_f16x2(unsigned x) {
    unsigned r;
    asm("ex2.approx.f16x2 %0, %1;" : "=r"(r) : "r"(x));
    return r;
}

__device__ __forceinline__ void mma_f16(
    float& c0, float& c1, float& c2, float& c3,
    unsigned a0, unsigned a1, unsigned a2, unsigned a3,
    unsigned b0, unsigned b1) {
    asm volatile(
        "mma.sync.aligned.m16n8k16.row.col.f32.f16.f16.f32 "
        "{%0,%1,%2,%3}, {%4,%5,%6,%7}, {%8,%9}, {%0,%1,%2,%3};"
        : "+f"(c0), "+f"(c1), "+f"(c2), "+f"(c3)
        : "r"(a0), "r"(a1), "r"(a2), "r"(a3), "r"(b0), "r"(b1));
}

__device__ __forceinline__ void ldsm_x4(
    unsigned& r0, unsigned& r1, unsigned& r2, unsigned& r3, unsigned addr) {
    asm volatile("ldmatrix.sync.aligned.m8n8.x4.shared.b16 {%0,%1,%2,%3}, [%4];"
                 : "=r"(r0), "=r"(r1), "=r"(r2), "=r"(r3) : "r"(addr));
}
__device__ __forceinline__ void ldsm_x4_t(
    unsigned& r0, unsigned& r1, unsigned& r2, unsigned& r3, unsigned addr) {
    asm volatile("ldmatrix.sync.aligned.m8n8.x4.trans.shared.b16 {%0,%1,%2,%3}, [%4];"
                 : "=r"(r0), "=r"(r1), "=r"(r2), "=r"(r3) : "r"(addr));
}

__device__ __forceinline__ unsigned smem_u32_of(const void* p) {
    unsigned r;
    asm("{ .reg .u64 t; cvta.to.shared.u64 t, %1; cvt.u32.u64 %0, t; }"
        : "=r"(r) : "l"(p));
    return r;
}

// ---------------- fused fp32 -> fp16 prep kernel -------------------------------
#define X_N4    (BT * D_MODEL / 4)          // 1048576
#define WIN_N4  (D3 * D_MODEL / 4)          // 786432
#define WOUT_N4 (D_MODEL * D_MODEL / 4)     // 262144
#define PREP_N4 (X_N4 + WIN_N4 + WOUT_N4)   // 2097152

__global__ __launch_bounds__(256) void prep_f16_kernel(
    const float* __restrict__ x, const float* __restrict__ w_in,
    const float* __restrict__ w_out,
    __half* __restrict__ xh, __half* __restrict__ winh, __half* __restrict__ wouth) {
    int i = blockIdx.x * 256 + threadIdx.x;
    const float* src;
    __half* dst;
    int off;
    if (i < X_N4)                 { src = x;     dst = xh;    off = i; }
    else if (i < X_N4 + WIN_N4)   { src = w_in;  dst = winh;  off = i - X_N4; }
    else if (i < PREP_N4)         { src = w_out; dst = wouth; off = i - X_N4 - WIN_N4; }
    else return;
    float4 v = ((const float4*)src)[off];
    uint2 u;
    u.x = pack_f16x2(v.x, v.y);
    u.y = pack_f16x2(v.z, v.w);
    ((uint2*)dst)[off] = u;
}

// ---------------- FP16 GEMM 64x128 tile (both projections; R16 best) ---------
#define KSTEP 64
#define HPAD  72
#define SOP_A_BYTES (64 * HPAD * 2)                    // 9216
#define SOP_W_BYTES (128 * HPAD * 2)                   // 18432
#define SSTAGE_BYTES (SOP_A_BYTES + SOP_W_BYTES)       // 27648
#define SGEMM_SMEM_BYTES (2 * SSTAGE_BYTES)             // 55296

template <int MODE>
__global__ __launch_bounds__(256, 3) void gemm_f16_kernel(
    const __half* __restrict__ A, const __half* __restrict__ W,
    float* __restrict__ C, int M, int N, int K) {
    extern __shared__ char smem[];
    const unsigned smem_u32 = smem_u32_of(smem);

    const int tid  = threadIdx.x;
    const int lane = tid & 31;
    const int wid  = tid >> 5;
    const int warp_m = wid & 1;
    const int warp_n = wid >> 1;
    const int bm = blockIdx.y * 64;
    const int bn = blockIdx.x * 128;
    const int lr = lane >> 2;
    const int lc = lane & 3;

    const int a_row = lane & 15;
    const int a_cb  = (lane >> 4) * 16;
    const int b_row = ((lane >> 4) << 3) + (lane & 7);
    const int b_cb  = (lane & 8) ? 16 : 0;

    const unsigned a_base0 = (unsigned)((warp_m * 32 + a_row) * 144 + a_cb);
    const unsigned a_base1 = (unsigned)((warp_m * 32 + 16 + a_row) * 144 + a_cb);
    unsigned b_base[2];
    #pragma unroll
    for (int jn = 0; jn < 2; jn++)
        b_base[jn] = (unsigned)(SOP_A_BYTES + (warp_n * 32 + jn * 16 + b_row) * 144 + b_cb);

#define SCOPY_TILE(k0, s) {                                                    \
        unsigned base_ = smem_u32 + (unsigned)((s) * SSTAGE_BYTES);            \
        _Pragma("unroll")                                                      \
        for (int it = 0; it < 2; it++) {                                       \
            int u_ = tid + 256 * it;                                           \
            int r_ = u_ >> 3, ch_ = u_ & 7;                                    \
            unsigned da_ = base_ + (unsigned)(r_ * 144 + ch_ * 16);            \
            asm volatile("cp.async.cg.shared.global [%0], [%1], 16;"           \
                :: "r"(da_), "l"(A + (size_t)(bm + r_) * K + (k0) + ch_ * 8)); \
        }                                                                      \
        _Pragma("unroll")                                                      \
        for (int it = 0; it < 4; it++) {                                       \
            int u_ = tid + 256 * it;                                           \
            int r_ = u_ >> 3, ch_ = u_ & 7;                                    \
            unsigned db_ = base_ + (unsigned)(SOP_A_BYTES + r_ * 144 + ch_ * 16);\
            asm volatile("cp.async.cg.shared.global [%0], [%1], 16;"           \
                :: "r"(db_), "l"(W + (size_t)(bn + r_) * K + (k0) + ch_ * 8)); \
        }                                                                      \
        asm volatile("cp.async.commit_group;"); }

    float acc[2][4][4];
    #pragma unroll
    for (int i = 0; i < 2; i++)
        #pragma unroll
        for (int j = 0; j < 4; j++)
            #pragma unroll
            for (int c = 0; c < 4; c++) acc[i][j][c] = 0.f;

    SCOPY_TILE(0, 0);

    const int nk = K / KSTEP;
    for (int i = 0; i < nk; i++) {
        asm volatile("cp.async.wait_group 0;");
        __syncthreads();
        if (i + 1 < nk) SCOPY_TILE((i + 1) * KSTEP, (i + 1) & 1);

        const unsigned sbase = smem_u32 + (unsigned)((i & 1) * SSTAGE_BYTES);
        #pragma unroll
        for (int kk = 0; kk < 4; kk++) {
            unsigned a[2][4];
            ldsm_x4(a[0][0], a[0][1], a[0][2], a[0][3], sbase + a_base0 + kk * 32);
            ldsm_x4(a[1][0], a[1][1], a[1][2], a[1][3], sbase + a_base1 + kk * 32);
            #pragma unroll
            for (int jn = 0; jn < 2; jn++) {
                unsigned r0, r1, r2, r3;
                ldsm_x4(r0, r1, r2, r3, sbase + b_base[jn] + kk * 32);
                int j0 = 2 * jn, j1 = 2 * jn + 1;
                mma_f16(acc[0][j0][0], acc[0][j0][1], acc[0][j0][2], acc[0][j0][3],
                        a[0][0], a[0][1], a[0][2], a[0][3], r0, r1);
                mma_f16(acc[1][j0][0], acc[1][j0][1], acc[1][j0][2], acc[1][j0][3],
                        a[1][0], a[1][1], a[1][2], a[1][3], r0, r1);
                mma_f16(acc[0][j1][0], acc[0][j1][1], acc[0][j1][2], acc[0][j1][3],
                        a[0][0], a[0][1], a[0][2], a[0][3], r2, r3);
                mma_f16(acc[1][j1][0], acc[1][j1][1], acc[1][j1][2], acc[1][j1][3],
                        a[1][0], a[1][1], a[1][2], a[1][3], r2, r3);
            }
        }
    }
#undef SCOPY_TILE

    #pragma unroll
    for (int i = 0; i < 2; i++) {
        #pragma unroll
        for (int j = 0; j < 4; j++) {
            #pragma unroll
            for (int half_row = 0; half_row < 2; half_row++) {
                int m = bm + warp_m * 32 + i * 16 + lr + half_row * 8;
                int n = bn + warp_n * 32 + j * 8 + 2 * lc;
                float v0 = acc[i][j][half_row * 2 + 0];
                float v1 = acc[i][j][half_row * 2 + 1];
                if (MODE == 0) {
                    int b = m >> 11;
                    int t = m & (SEQ - 1);
                    int which = n >> 10;
                    int d = n & (D_MODEL - 1);
                    int h = d >> 6;
                    int hd = d & 63;
                    if (which == 0) { v0 *= 0.125f; v1 *= 0.125f; }
                    size_t dst = (size_t)which * ((size_t)BT * D_MODEL) +
                                 (((size_t)(b * N_HEADS + h) * SEQ + t) << 6) + hd;
                    *(unsigned*)((__half*)C + dst) = pack_f16x2(v0, v1);
                } else {
                    C[(size_t)m * N + n]     = v0;
                    C[(size_t)m * N + n + 1] = v1;
                }
            }
        }
    }
}

// ---------------- FP16 tensor-core causal flash attention --------------------
// R16 structure; exp via ex2.approx.f16x2 (half the MUFU ops, fused with pack).
#define QT 128
#define KT 64
#define ATT_OP_BYTES   (KT * HPAD * 2)                 // 9216
#define ATT_STAGE_BYTES (2 * ATT_OP_BYTES)             // 18432
#define ATT_SMEM_BYTES  (2 * ATT_STAGE_BYTES)           // 36864
#define ONES_F16X2 0x3C003C00u
#define LOG2E 1.4426950408889634f

__global__ __launch_bounds__(256) void attn_f16_kernel(
    const __half* __restrict__ qkv, __half* __restrict__ out) {
    extern __shared__ char asmem[];
    const unsigned sm0 = smem_u32_of(asmem);

    const int tid  = threadIdx.x;
    const int lane = tid & 31;
    const int wid  = tid >> 5;
    const int lr = lane >> 2;
    const int lc = lane & 3;

    const int bh = blockIdx.y;
    const int qt = (gridDim.x - 1) - blockIdx.x;   // heavy tiles first
    const int q0 = qt * QT;

    const __half* Qp = qkv + ((size_t)bh * SEQ + q0) * DH;
    const __half* Kp = qkv + (size_t)BT * D_MODEL + (size_t)bh * SEQ * DH;
    const __half* Vp = qkv + (size_t)2 * BT * D_MODEL + (size_t)bh * SEQ * DH;

    const int kb_row = ((lane >> 4) << 3) + (lane & 7);
    const int kb_cb  = (lane & 8) ? 16 : 0;
    const int vb_row = ((lane & 8) ? 8 : 0) + (lane & 7);
    const int vb_cb  = (lane >> 4) * 16;

#define ATT_COPY(k0, s) {                                                      \
        unsigned base_ = sm0 + (unsigned)((s) * ATT_STAGE_BYTES);              \
        _Pragma("unroll")                                                      \
        for (int it = 0; it < 2; it++) {                                       \
            int i_ = tid + 256 * it;                                           \
            int r_ = i_ >> 3;                                                  \
            int ch_ = i_ & 7;                                                  \
            unsigned kd_ = base_ + (unsigned)(r_ * 144 + ch_ * 16);            \
            asm volatile("cp.async.cg.shared.global [%0], [%1], 16;"           \
                :: "r"(kd_), "l"(Kp + (size_t)((k0) + r_) * DH + ch_ * 8));    \
            unsigned vd_ = base_ + (unsigned)(ATT_OP_BYTES + r_ * 144 + ch_ * 16);\
            asm volatile("cp.async.cg.shared.global [%0], [%1], 16;"           \
                :: "r"(vd_), "l"(Vp + (size_t)((k0) + r_) * DH + ch_ * 8));    \
        }                                                                      \
        asm volatile("cp.async.commit_group;"); }

    unsigned qa[4][4];
    {
        const int r0 = wid * 16 + lr;
        #pragma unroll
        for (int kk = 0; kk < 4; kk++) {
            int c = kk * 16 + 2 * lc;
            qa[kk][0] = *(const unsigned*)&Qp[(size_t)r0 * DH + c];
            qa[kk][1] = *(const unsigned*)&Qp[(size_t)(r0 + 8) * DH + c];
            qa[kk][2] = *(const unsigned*)&Qp[(size_t)r0 * DH + c + 8];
            qa[kk][3] = *(const unsigned*)&Qp[(size_t)(r0 + 8) * DH + c + 8];
        }
    }

    float o[8][4];
    #pragma unroll
    for (int n = 0; n < 8; n++)
        #pragma unroll
        for (int c = 0; c < 4; c++) o[n][c] = 0.f;
    float m0 = -1e30f, m1 = -1e30f, l0 = 0.f, l1 = 0.f;

    const int nkt = 2 * qt + 2;
    const int row0 = q0 + wid * 16 + lr;
    const int row1 = row0 + 8;

    ATT_COPY(0, 0);

    for (int kt = 0; kt < nkt; kt++) {
        const int k0 = kt * KT;
        const int s = kt & 1;
        asm volatile("cp.async.wait_group 0;");
        __syncthreads();
        if (kt + 1 < nkt) ATT_COPY((kt + 1) * KT, s ^ 1);

        const unsigned ksbase = sm0 + (unsigned)(s * ATT_STAGE_BYTES);

        // ---- S = (Q/8) @ K^T ----
        float sv[8][4];
        #pragma unroll
        for (int n = 0; n < 8; n++)
            #pragma unroll
            for (int c = 0; c < 4; c++) sv[n][c] = 0.f;

        #pragma unroll
        for (int kk = 0; kk < 4; kk++) {
            #pragma unroll
            for (int jn = 0; jn < 4; jn++) {
                unsigned r0, r1, r2, r3;
                ldsm_x4(r0, r1, r2, r3,
                        ksbase + (unsigned)((jn * 16 + kb_row) * 144 + kk * 32 + kb_cb));
                int n0 = 2 * jn, n1 = 2 * jn + 1;
                mma_f16(sv[n0][0], sv[n0][1], sv[n0][2], sv[n0][3],
                        qa[kk][0], qa[kk][1], qa[kk][2], qa[kk][3], r0, r1);
                mma_f16(sv[n1][0], sv[n1][1], sv[n1][2], sv[n1][3],
                        qa[kk][0], qa[kk][1], qa[kk][2], qa[kk][3], r2, r3);
            }
        }

        if (kt >= 2 * qt) {
            #pragma unroll
            for (int n = 0; n < 8; n++) {
                int col0 = k0 + n * 8 + 2 * lc;
                if (col0 > row0)     sv[n][0] = -1e30f;
                if (col0 + 1 > row0) sv[n][1] = -1e30f;
                if (col0 > row1)     sv[n][2] = -1e30f;
                if (col0 + 1 > row1) sv[n][3] = -1e30f;
            }
        }

        // ---- online softmax: max reduce ----
        float mx0 = -1e30f, mx1 = -1e30f;
        #pragma unroll
        for (int n = 0; n < 8; n++) {
            mx0 = fmaxf(mx0, fmaxf(sv[n][0], sv[n][1]));
            mx1 = fmaxf(mx1, fmaxf(sv[n][2], sv[n][3]));
        }
        mx0 = fmaxf(mx0, __shfl_xor_sync(0xffffffffu, mx0, 1));
        mx0 = fmaxf(mx0, __shfl_xor_sync(0xffffffffu, mx0, 2));
        mx1 = fmaxf(mx1, __shfl_xor_sync(0xffffffffu, mx1, 1));
        mx1 = fmaxf(mx1, __shfl_xor_sync(0xffffffffu, mx1, 2));

        float mn0 = fmaxf(m0, mx0), mn1 = fmaxf(m1, mx1);
        float alpha0 = __expf(m0 - mn0), alpha1 = __expf(m1 - mn1);
        m0 = mn0; m1 = mn1;

        // ---- P = exp(S - m) via ex2.approx.f16x2 (fused exp + fp16 pack) ----
        const float mnl0 = mn0 * LOG2E;
        const float mnl1 = mn1 * LOG2E;
        unsigned pfrag[4][4];
        #pragma unroll
        for (int kk = 0; kk < 4; kk++) {
            float t00 = fmaf(sv[2 * kk][0],     LOG2E, -mnl0);
            float t01 = fmaf(sv[2 * kk][1],     LOG2E, -mnl0);
            float t02 = fmaf(sv[2 * kk][2],     LOG2E, -mnl1);
            float t03 = fmaf(sv[2 * kk][3],     LOG2E, -mnl1);
            float t10 = fmaf(sv[2 * kk + 1][0], LOG2E, -mnl0);
            float t11 = fmaf(sv[2 * kk + 1][1], LOG2E, -mnl0);
            float t12 = fmaf(sv[2 * kk + 1][2], LOG2E, -mnl1);
            float t13 = fmaf(sv[2 * kk + 1][3], LOG2E, -mnl1);
            pfrag[kk][0] = ex2_f16x2(pack_f16x2(t00, t01));
            pfrag[kk][1] = ex2_f16x2(pack_f16x2(t02, t03));
            pfrag[kk][2] = ex2_f16x2(pack_f16x2(t10, t11));
            pfrag[kk][3] = ex2_f16x2(pack_f16x2(t12, t13));
        }

        // ---- row sums via HMMA with B = ones ----
        float sc0 = 0.f, sc1 = 0.f, sc2 = 0.f, sc3 = 0.f;
        #pragma unroll
        for (int kk = 0; kk < 4; kk++)
            mma_f16(sc0, sc1, sc2, sc3,
                    pfrag[kk][0], pfrag[kk][1], pfrag[kk][2], pfrag[kk][3],
                    ONES_F16X2, ONES_F16X2);
        l0 = l0 * alpha0 + sc0;
        l1 = l1 * alpha1 + sc2;

        #pragma unroll
        for (int n = 0; n < 8; n++) {
            o[n][0] *= alpha0; o[n][1] *= alpha0;
            o[n][2] *= alpha1; o[n][3] *= alpha1;
        }

        // ---- O += P @ V ----
        #pragma unroll
        for (int kk = 0; kk < 4; kk++) {
            #pragma unroll
            for (int dm = 0; dm < 4; dm++) {
                unsigned r0, r1, r2, r3;
                ldsm_x4_t(r0, r1, r2, r3,
                          ksbase + (unsigned)(ATT_OP_BYTES +
                              (kk * 16 + vb_row) * 144 + dm * 32 + vb_cb));
                int n0 = 2 * dm, n1 = 2 * dm + 1;
                mma_f16(o[n0][0], o[n0][1], o[n0][2], o[n0][3],
                        pfrag[kk][0], pfrag[kk][1], pfrag[kk][2], pfrag[kk][3],
                        r0, r1);
                mma_f16(o[n1][0], o[n1][1], o[n1][2], o[n1][3],
                        pfrag[kk][0], pfrag[kk][1], pfrag[kk][2], pfrag[kk][3],
                        r2, r3);
            }
        }
    }
#undef ATT_COPY

    const int b = bh >> 4;
    const int h = bh & 15;
    const float inv0 = 1.f / l0;
    const float inv1 = 1.f / l1;
    #pragma unroll
    for (int n = 0; n < 8; n++) {
        int d = h * DH + n * 8 + 2 * lc;
        *(unsigned*)&out[((size_t)(b * SEQ + row0)) * D_MODEL + d] =
            pack_f16x2(o[n][0] * inv0, o[n][1] * inv0);
        *(unsigned*)&out[((size_t)(b * SEQ + row1)) * D_MODEL + d] =
            pack_f16x2(o[n][2] * inv1, o[n][3] * inv1);
    }
}

// ---------------- launch ------------------------------------------------------
extern "C" void kernel_launch(void* const* d_in, const int* in_sizes, int n_in,
                              void* d_out, int out_size) {
    const float* x     = (const float*)d_in[0];
    const float* W_in  = (const float*)d_in[1];
    const float* W_out = (const float*)d_in[2];
    float* out = (float*)d_out;

    __half *xh, *winh, *wouth, *qkvh, *attnh;
    cudaGetSymbolAddress((void**)&xh,    g_xh);
    cudaGetSymbolAddress((void**)&winh,  g_winh);
    cudaGetSymbolAddress((void**)&wouth, g_wouth);
    cudaGetSymbolAddress((void**)&qkvh,  g_qkvh);
    cudaGetSymbolAddress((void**)&attnh, g_attnh);

    cudaFuncSetAttribute(gemm_f16_kernel<0>,
                         cudaFuncAttributeMaxDynamicSharedMemorySize, SGEMM_SMEM_BYTES);
    cudaFuncSetAttribute(gemm_f16_kernel<1>,
                         cudaFuncAttributeMaxDynamicSharedMemorySize, SGEMM_SMEM_BYTES);
    cudaFuncSetAttribute(attn_f16_kernel,
                         cudaFuncAttributeMaxDynamicSharedMemorySize, ATT_SMEM_BYTES);

    // 0. fused conversion of all three inputs to fp16
    prep_f16_kernel<<<(PREP_N4 + 255) / 256, 256>>>(x, W_in, W_out, xh, winh, wouth);

    // 1. QKV projection (64x128 tile, 3 CTA/SM)
    {
        dim3 grid(D3 / 128, BT / 64);         // (24, 64) = 1536 CTAs
        gemm_f16_kernel<0><<<grid, 256, SGEMM_SMEM_BYTES>>>(
            xh, winh, (float*)qkvh, BT, D3, D_MODEL);
    }

    // 2. causal flash attention (fp16 mma, ex2.f16x2 softmax)
    {
        dim3 grid(SEQ / QT, BATCH * N_HEADS); // (16, 32) = 512 CTAs
        attn_f16_kernel<<<grid, 256, ATT_SMEM_BYTES>>>(qkvh, attnh);
    }

    // 3. output projection (64x128 tile) -> fp32 d_out
    {
        dim3 grid(D_MODEL / 128, BT / 64);    // (8, 64) = 512 CTAs
        gemm_f16_kernel<1><<<grid, 256, SGEMM_SMEM_BYTES>>>(
            attnh, wouth, out, BT, D_MODEL, D_MODEL);
    }
}